// round 14
// baseline (speedup 1.0000x reference)
#include <cuda_runtime.h>
#include <cuda_bf16.h>
#include <math.h>
#include <stdint.h>
#include <stddef.h>

#define N_LAYER 6
#define B_  2
#define T_  512
#define D_  256
#define NH  4
#define NN  4096
#define V_  256
#define BH  (B_ * NH)
#define TT_ (T_ * T_)
#define LN_EPS 1e-5f
#define TWO_PI 6.283185307179586f

typedef __nv_bfloat16 bf16;

#if defined(__CUDA_ARCH__) && (defined(__CUDA_ARCH_FEAT_SM103_ALL) || \
    defined(__CUDA_ARCH_FEAT_SM100_ALL) || defined(__CUDA_ARCH_SPECIFIC__) || \
    defined(__CUDA_ARCH_FAMILY_SPECIFIC__))
#define HAS_TC 1
#else
#define HAS_TC 0
#endif

// ---------------- scratch (device globals; no allocation allowed) ----------
__device__ __align__(256) float g_x    [B_ * T_ * D_];
__device__ __align__(256) float g_spart[4 * BH * TT_];
__device__ __align__(256) float g_ykv  [BH * T_ * D_];
__device__ __align__(256) float g_ypart[BH * 4 * T_ * D_];
__device__ __align__(256) float g_cos  [T_ * NN];
__device__ __align__(256) float g_sin  [T_ * NN];
// packed bf16 hi/lo planes: row layout = per 32-k chunk [hi0..31 | lo0..31]
__device__ __align__(256) bf16 g_xpk   [B_ * T_ * 2 * D_];
__device__ __align__(256) bf16 g_xtpk  [B_ * D_ * 2 * T_];
__device__ __align__(256) bf16 g_qrpk  [BH * T_ * 2 * NN];   // rope(x_sparse); xs recovered by inverse rope
__device__ __align__(256) bf16 g_spk   [BH * T_ * 2 * T_];
__device__ __align__(256) bf16 g_ykvpk [BH * T_ * 2 * D_];
__device__ __align__(256) bf16 g_xypk  [BH * T_ * 2 * NN];   // xy_sparse (packed)
__device__ __align__(256) bf16 g_encpkt [NH * NN * 2 * D_];
__device__ __align__(256) bf16 g_encvpkt[NH * NN * 2 * D_];
__device__ __align__(256) bf16 g_decpkt [NH * D_ * 2 * NN];

__constant__ int c_pair_tt[10] = {0,1,1,2,2,2,3,3,3,3};
__constant__ int c_pair_st[10] = {0,0,1,0,1,2,0,1,2,3};

__device__ __forceinline__ float blk_sum(float v) {
    __shared__ float sh[8];
    #pragma unroll
    for (int o = 16; o > 0; o >>= 1) v += __shfl_xor_sync(0xffffffffu, v, o);
    __syncthreads();
    if ((threadIdx.x & 31) == 0) sh[threadIdx.x >> 5] = v;
    __syncthreads();
    float t = 0.f;
    #pragma unroll
    for (int i = 0; i < 8; ++i) t += sh[i];
    return t;
}

__device__ __forceinline__ uint32_t pack2(float a, float b) {
    __nv_bfloat162 t = __floats2bfloat162_rn(a, b);
    return *reinterpret_cast<uint32_t*>(&t);
}
__device__ __forceinline__ void split2(float v, float& hf, float& lf) {
    __nv_bfloat16 h = __float2bfloat16(v);
    hf = __bfloat162float(h);
    lf = v - hf;
}

#define ROWI(i) ((ty << 2) + ((i) & 3) + (((i) >> 2) << 6))
#define COLJ(j) ((tx2 << 2) + ((j) & 3) + (((j) >> 2) << 6))

__device__ __forceinline__ void st_pk_pair(bf16* __restrict__ dst, size_t rowbase,
                                           int n, float v0, float v1) {
    size_t p = rowbase + (((size_t)(n >> 5)) << 6) + (n & 31);
    float h0, l0, h1, l1;
    split2(v0, h0, l0); split2(v1, h1, l1);
    dst[p]      = __float2bfloat16(h0);
    dst[p + 1]  = __float2bfloat16(h1);
    dst[p + 32] = __float2bfloat16(l0);
    dst[p + 33] = __float2bfloat16(l1);
}

__device__ __forceinline__ void ld_pk_pair(const bf16* __restrict__ src, size_t rowbase,
                                           int n, float& v0, float& v1) {
    size_t p = rowbase + (((size_t)(n >> 5)) << 6) + (n & 31);
    v0 = __bfloat162float(src[p])     + __bfloat162float(src[p + 32]);
    v1 = __bfloat162float(src[p + 1]) + __bfloat162float(src[p + 33]);
}

#if HAS_TC
// =================== tcgen05 path ===========================================
__device__ __forceinline__ uint32_t smem_u32(const void* p) {
    return (uint32_t)__cvta_generic_to_shared(p);
}
__device__ __forceinline__ uint32_t elect1() {
    uint32_t pred;
    asm volatile("{\n\t.reg .pred p;\n\telect.sync _|p, 0xFFFFFFFF;\n\t"
                 "selp.b32 %0, 1, 0, p;\n\t}" : "=r"(pred));
    return pred;
}

#define SWZ(off) ((off) ^ (((off) >> 3) & 0x70))

#define MBAR_INIT(a, n) \
    asm volatile("mbarrier.init.shared.b64 [%0], %1;" :: "r"(a), "r"(n) : "memory")
#define MBAR_INVAL(a) \
    asm volatile("mbarrier.inval.shared.b64 [%0];" :: "r"(a) : "memory")
#define MBAR_WAIT(a, ph) do {                                                  \
    asm volatile("{\n\t.reg .pred P1;\n\t"                                     \
        "WL_%=:\n\t"                                                           \
        "mbarrier.try_wait.parity.acquire.cta.shared::cta.b64 P1, [%0], %1, 0x989680;\n\t" \
        "@P1 bra.uni WD_%=;\n\t"                                               \
        "bra.uni WL_%=;\n\t"                                                   \
        "WD_%=:\n\t}" :: "r"(a), "r"(ph) : "memory");                          \
} while (0)

#define TC_ALLOC(sa, n) \
    asm volatile("tcgen05.alloc.cta_group::1.sync.aligned.shared::cta.b32 [%0], %1;" \
                 :: "r"(sa), "r"(n) : "memory")
#define TC_RELINQ() \
    asm volatile("tcgen05.relinquish_alloc_permit.cta_group::1.sync.aligned;")
#define TC_DEALLOC(t, n) \
    asm volatile("tcgen05.dealloc.cta_group::1.sync.aligned.b32 %0, %1;" :: "r"(t), "r"(n))
#define TC_COMMIT(a) \
    asm volatile("tcgen05.commit.cta_group::1.mbarrier::arrive::one.shared::cluster.b64 [%0];" \
                 :: "r"(a) : "memory")
#define TC_FENCE_AFTER()  asm volatile("tcgen05.fence::after_thread_sync;" ::: "memory")
#define TC_FENCE_BEFORE() asm volatile("tcgen05.fence::before_thread_sync;" ::: "memory")
#define FENCE_ASYNC() asm volatile("fence.proxy.async.shared::cta;" ::: "memory")
#define TC_WAIT_LD() asm volatile("tcgen05.wait::ld.sync.aligned;" ::: "memory")

#define LDTM32(r, addr)                                                        \
    asm volatile("tcgen05.ld.sync.aligned.32x32b.x32.b32 "                     \
        "{%0,%1,%2,%3,%4,%5,%6,%7,%8,%9,%10,%11,%12,%13,%14,%15,"             \
        "%16,%17,%18,%19,%20,%21,%22,%23,%24,%25,%26,%27,%28,%29,%30,%31},[%32];" \
        : "=r"((r)[0]),"=r"((r)[1]),"=r"((r)[2]),"=r"((r)[3]),                \
          "=r"((r)[4]),"=r"((r)[5]),"=r"((r)[6]),"=r"((r)[7]),                \
          "=r"((r)[8]),"=r"((r)[9]),"=r"((r)[10]),"=r"((r)[11]),              \
          "=r"((r)[12]),"=r"((r)[13]),"=r"((r)[14]),"=r"((r)[15]),            \
          "=r"((r)[16]),"=r"((r)[17]),"=r"((r)[18]),"=r"((r)[19]),            \
          "=r"((r)[20]),"=r"((r)[21]),"=r"((r)[22]),"=r"((r)[23]),            \
          "=r"((r)[24]),"=r"((r)[25]),"=r"((r)[26]),"=r"((r)[27]),            \
          "=r"((r)[28]),"=r"((r)[29]),"=r"((r)[30]),"=r"((r)[31])             \
        : "r"(addr))

static __device__ __forceinline__ uint64_t mk_desc(uint32_t addr) {
    return ((uint64_t)2 << 61) | ((uint64_t)1 << 46) | ((uint64_t)64 << 32)
         | ((uint64_t)1 << 16) | (uint64_t)((addr >> 4) & 0x3FFF);
}

#define IDESC_F16 0x08200490u   // dtype=F32, a/b=BF16, N=128, M=128

__device__ __forceinline__ void mma_ss(uint32_t d, uint64_t ad, uint64_t bd, uint32_t en) {
    asm volatile("{\n\t.reg .pred p;\n\tsetp.ne.u32 p,%4,0;\n\t"
        "tcgen05.mma.cta_group::1.kind::f16 [%0], %1, %2, %3, {%5,%5,%5,%5}, p;\n\t}"
        :: "r"(d), "l"(ad), "l"(bd), "r"(IDESC_F16), "r"(en), "r"(0u) : "memory");
}

#define SM_TM  0
#define SM_BAR 8
#define SM_A   1024
#define SM_B   (1024 + 16384)
#define SM_SZ  (1024 + 32768)

// D = A * B^T, 128x128 fp32 tile; 3-term bf16 split; serial per chunk (R9).
__device__ uint32_t run_mma(char* sm, const bf16* __restrict__ A, size_t lda,
                            const bf16* __restrict__ Bm, size_t ldb, int nchunk) {
    const uint32_t sb = smem_u32(sm);
    const int tid = threadIdx.x, wid = tid >> 5;
    if (tid == 0) MBAR_INIT(sb + SM_BAR, 1);
    if (wid == 0) TC_ALLOC(sb + SM_TM, 128);
    __syncthreads();
    uint32_t tmem;
    asm volatile("ld.shared.b32 %0, [%1];" : "=r"(tmem) : "r"(sb + SM_TM));
    const uint64_t adesc = mk_desc(sb + SM_A);
    const uint64_t bdesc = mk_desc(sb + SM_B);

    const int row  = tid >> 1;
    const int half = (tid & 1) << 6;
    const char* gA = (const char*)(A + (size_t)row * lda) + half;
    const char* gB = (const char*)(Bm + (size_t)row * ldb) + half;
    char* sA[4]; char* sBp[4];
    #pragma unroll
    for (int i = 0; i < 4; ++i) {
        int off = row * 128 + half + i * 16;
        sA[i]  = sm + SM_A + SWZ(off);
        sBp[i] = sm + SM_B + SWZ(off);
    }

    for (int c = 0; c < nchunk; ++c) {
        #pragma unroll
        for (int i = 0; i < 4; ++i) {
            *(uint4*)sA[i]  = *(const uint4*)(gA + (size_t)c * 128 + i * 16);
            *(uint4*)sBp[i] = *(const uint4*)(gB + (size_t)c * 128 + i * 16);
        }
        __syncthreads();
        if (wid == 0 && elect1()) {
            FENCE_ASYNC();
            mma_ss(tmem, adesc + 0, bdesc + 0, c != 0);
            mma_ss(tmem, adesc + 2, bdesc + 2, 1);
            mma_ss(tmem, adesc + 0, bdesc + 4, 1);
            mma_ss(tmem, adesc + 2, bdesc + 6, 1);
            mma_ss(tmem, adesc + 4, bdesc + 0, 1);
            mma_ss(tmem, adesc + 6, bdesc + 2, 1);
            TC_COMMIT(sb + SM_BAR);
        }
        MBAR_WAIT(sb + SM_BAR, c & 1);
        __syncthreads();
    }
    TC_FENCE_AFTER();
    return tmem;
}

__device__ __forceinline__ void finish_mma(char* sm, uint32_t tmem) {
    TC_FENCE_BEFORE();
    __syncthreads();
    const uint32_t sb = smem_u32(sm);
    if (threadIdx.x == 0) MBAR_INVAL(sb + SM_BAR);
    if ((threadIdx.x >> 5) == 0) {
        TC_RELINQ();
        TC_DEALLOC(tmem, 128);
    }
}
#else
// =================== SIMT fallback path =====================================
__device__ __forceinline__ float4 ldpk4(const bf16* __restrict__ rowp, int k) {
    const bf16* p = rowp + ((k >> 5) << 6) + (k & 31);
    uint2 h = *(const uint2*)p;
    uint2 l = *(const uint2*)(p + 32);
    float2 fh0 = __bfloat1622float2(*(__nv_bfloat162*)&h.x);
    float2 fh1 = __bfloat1622float2(*(__nv_bfloat162*)&h.y);
    float2 fl0 = __bfloat1622float2(*(__nv_bfloat162*)&l.x);
    float2 fl1 = __bfloat1622float2(*(__nv_bfloat162*)&l.y);
    return make_float4(fh0.x + fl0.x, fh0.y + fl0.y, fh1.x + fl1.x, fh1.y + fl1.y);
}

__device__ void gemm128p(const bf16* __restrict__ A, int lda,
                         const bf16* __restrict__ B, int ldb,
                         int K, float acc[8][8]) {
    __shared__ float As[16][128];
    __shared__ float Bs[16][128];
    const int tx  = threadIdx.x;
    const int ty  = tx >> 4;
    const int tx2 = tx & 15;
    const int am = tx >> 2;
    const int ak = (tx & 3) << 2;
    for (int k0 = 0; k0 < K; k0 += 16) {
        float4 a0 = ldpk4(A + (size_t)am * lda, k0 + ak);
        float4 a1 = ldpk4(A + (size_t)(am + 64) * lda, k0 + ak);
        float4 b0 = ldpk4(B + (size_t)am * ldb, k0 + ak);
        float4 b1 = ldpk4(B + (size_t)(am + 64) * ldb, k0 + ak);
        As[ak+0][am] = a0.x; As[ak+1][am] = a0.y; As[ak+2][am] = a0.z; As[ak+3][am] = a0.w;
        As[ak+0][am+64] = a1.x; As[ak+1][am+64] = a1.y; As[ak+2][am+64] = a1.z; As[ak+3][am+64] = a1.w;
        Bs[ak+0][am] = b0.x; Bs[ak+1][am] = b0.y; Bs[ak+2][am] = b0.z; Bs[ak+3][am] = b0.w;
        Bs[ak+0][am+64] = b1.x; Bs[ak+1][am+64] = b1.y; Bs[ak+2][am+64] = b1.z; Bs[ak+3][am+64] = b1.w;
        __syncthreads();
        #pragma unroll
        for (int k = 0; k < 16; ++k) {
            float4 va0 = *(const float4*)&As[k][ty << 2];
            float4 va1 = *(const float4*)&As[k][64 + (ty << 2)];
            float4 vb0 = *(const float4*)&Bs[k][tx2 << 2];
            float4 vb1 = *(const float4*)&Bs[k][64 + (tx2 << 2)];
            float av[8] = {va0.x, va0.y, va0.z, va0.w, va1.x, va1.y, va1.z, va1.w};
            float bv[8] = {vb0.x, vb0.y, vb0.z, vb0.w, vb1.x, vb1.y, vb1.z, vb1.w};
            #pragma unroll
            for (int i = 0; i < 8; ++i)
                #pragma unroll
                for (int j = 0; j < 8; ++j)
                    acc[i][j] += av[i] * bv[j];
        }
        __syncthreads();
    }
}
#endif  // HAS_TC

// ---------------- elementwise / setup kernels -------------------------------
__global__ void k_tables() {
    int idx = blockIdx.x * 256 + threadIdx.x;
    int t = idx >> 12;
    int n = idx & (NN - 1);
    float qidx = (float)((n >> 1) << 1);
    float e = qidx / (float)NN;
    float freq = 1.0f / powf(65536.0f, e) / TWO_PI;
    float phase = (float)t * freq;
    float ph = (phase - floorf(phase)) * TWO_PI;
    float s, c;
    sincosf(ph, &s, &c);
    g_cos[idx] = c;
    g_sin[idx] = s;
}

__global__ void k_tpack(const float* __restrict__ ext, int mode) {
    __shared__ float tile[32][33];
    const float* src; bf16* dst; int lds, ldd; size_t ss, ds;
    if (mode == 0)      { src = ext; dst = g_encpkt;  lds = NN; ldd = 512;  ss = (size_t)D_*NN; ds = (size_t)NN*512; }
    else if (mode == 1) { src = ext; dst = g_encvpkt; lds = NN; ldd = 512;  ss = (size_t)D_*NN; ds = (size_t)NN*512; }
    else if (mode == 2) { src = ext; dst = g_decpkt;  lds = D_; ldd = 8192; ss = (size_t)NN*D_; ds = (size_t)D_*8192; }
    else                { src = g_x; dst = g_xtpk;    lds = D_; ldd = 1024; ss = (size_t)T_*D_; ds = (size_t)D_*1024; }
    src += (size_t)blockIdx.z * ss;
    dst += (size_t)blockIdx.z * ds;
    int c0 = blockIdx.x << 5, r0 = blockIdx.y << 5;
    int tx = threadIdx.x & 31, ty = threadIdx.x >> 5;
    #pragma unroll
    for (int i = 0; i < 4; ++i) {
        int r = r0 + ty + (i << 3);
        tile[ty + (i << 3)][tx] = src[(size_t)r * lds + c0 + tx];
    }
    __syncthreads();
    #pragma unroll
    for (int i = 0; i < 4; ++i) {
        int c = c0 + ty + (i << 3);
        float v = tile[tx][ty + (i << 3)];
        float hf, lf; split2(v, hf, lf);
        size_t base = (size_t)c * ldd + ((size_t)(r0 >> 5) << 6) + tx;
        dst[base]      = __float2bfloat16(hf);
        dst[base + 32] = __float2bfloat16(lf);
    }
}

__global__ void k_embed(const int* __restrict__ ids, const float* __restrict__ table) {
    int bt = blockIdx.x;
    int d  = threadIdx.x;
    float v = table[(size_t)ids[bt] * D_ + d];
    float mu  = blk_sum(v) * (1.0f / D_);
    float dv  = v - mu;
    float var = blk_sum(dv * dv) * (1.0f / D_);
    float r = dv / sqrtf(var + LN_EPS);
    g_x[(size_t)bt * D_ + d] = r;
    float hf, lf; split2(r, hf, lf);
    size_t p = (size_t)bt * 512 + ((d >> 5) << 6) + (d & 31);
    g_xpk[p]      = __float2bfloat16(hf);
    g_xpk[p + 32] = __float2bfloat16(lf);
}

// ---------------- main GEMM kernels -----------------------------------------
__global__ __launch_bounds__(256) __cluster_dims__(1, 1, 1)
void k_enc_tc(int which) {   // 0 = encoder (rope->qrpk), 1 = encoder_v (xy; xs via inverse rope)
    const int bh = blockIdx.z;
    const int b = bh >> 2, h = bh & 3;
    const int tt = blockIdx.y << 7, nn0 = blockIdx.x << 7;
    const bf16* A = which ? g_ykvpk + (size_t)bh * T_ * 512 + (size_t)tt * 512
                          : g_xpk + (size_t)b * T_ * 512 + (size_t)tt * 512;
    const bf16* Bw = (which ? g_encvpkt : g_encpkt) + (size_t)h * NN * 512 + (size_t)nn0 * 512;
#if HAS_TC
    __shared__ __align__(1024) char sm[SM_SZ];
    uint32_t tmem = run_mma(sm, A, 512, Bw, 512, 8);
    const int wid = threadIdx.x >> 5, lane = threadIdx.x & 31;
    if (wid < 4) {
        const int t = tt + wid * 32 + lane;
        const size_t qrow = ((size_t)bh * T_ + t) * (2 * NN) + ((size_t)(nn0 >> 5) << 6);
        #pragma unroll
        for (int g = 0; g < 4; ++g) {
            uint32_t d[32];
            LDTM32(d, tmem + g * 32);
            TC_WAIT_LD();
            float v[32];
            #pragma unroll
            for (int j = 0; j < 32; ++j) v[j] = fmaxf(__uint_as_float(d[j]), 0.f);
            uint32_t whi[16], wlo[16];
            const float* crow = g_cos + (size_t)t * NN + nn0 + g * 32;
            const float* srow = g_sin + (size_t)t * NN + nn0 + g * 32;
            if (which == 0) {
                // rope + pack qr (xs NOT stored; recovered by inverse rope in pass 1)
                #pragma unroll
                for (int j = 0; j < 32; j += 2) {
                    float cs = crow[j], sn = srow[j];
                    float qe = v[j] * cs - v[j+1] * sn;
                    float qo = v[j+1] * cs + v[j] * sn;
                    float he, le, ho, lo2;
                    split2(qe, he, le); split2(qo, ho, lo2);
                    whi[j >> 1] = pack2(he, ho);
                    wlo[j >> 1] = pack2(le, lo2);
                }
                uint4* qp = (uint4*)&g_qrpk[qrow + g * 64];
                #pragma unroll
                for (int i = 0; i < 4; ++i)
                    qp[i] = make_uint4(whi[i*4], whi[i*4+1], whi[i*4+2], whi[i*4+3]);
                #pragma unroll
                for (int i = 0; i < 4; ++i)
                    qp[4 + i] = make_uint4(wlo[i*4], wlo[i*4+1], wlo[i*4+2], wlo[i*4+3]);
            } else {
                // xs = R^-1 * qr (read packed qr), then xy = xs * relu(acc)
                const uint4* qp = (const uint4*)&g_qrpk[qrow + g * 64];
                #pragma unroll
                for (int i = 0; i < 4; ++i) {
                    uint4 hh = qp[i], ll = qp[4 + i];
                    uint32_t hw[4] = {hh.x, hh.y, hh.z, hh.w};
                    uint32_t lw[4] = {ll.x, ll.y, ll.z, ll.w};
                    #pragma unroll
                    for (int q = 0; q < 4; ++q) {
                        float2 fh = __bfloat1622float2(*(__nv_bfloat162*)&hw[q]);
                        float2 fl = __bfloat1622float2(*(__nv_bfloat162*)&lw[q]);
                        int j = (i * 4 + q) * 2;
                        float qe = fh.x + fl.x, qo = fh.y + fl.y;
                        float cs = crow[j], sn = srow[j];
                        float xe = qe * cs + qo * sn;      // inverse rotation
                        float xo = qo * cs - qe * sn;
                        v[j]   = xe * v[j];
                        v[j+1] = xo * v[j+1];
                    }
                }
                #pragma unroll
                for (int j = 0; j < 32; j += 2) {
                    float h0, l0, h1, l1;
                    split2(v[j], h0, l0); split2(v[j+1], h1, l1);
                    whi[j >> 1] = pack2(h0, h1);
                    wlo[j >> 1] = pack2(l0, l1);
                }
                uint4* yp = (uint4*)&g_xypk[qrow + g * 64];
                #pragma unroll
                for (int i = 0; i < 4; ++i)
                    yp[i] = make_uint4(whi[i*4], whi[i*4+1], whi[i*4+2], whi[i*4+3]);
                #pragma unroll
                for (int i = 0; i < 4; ++i)
                    yp[4 + i] = make_uint4(wlo[i*4], wlo[i*4+1], wlo[i*4+2], wlo[i*4+3]);
            }
        }
    }
    finish_mma(sm, tmem);
#else
    float acc[8][8] = {};
    gemm128p(A, 512, Bw, 512, D_, acc);
    const int tx = threadIdx.x, ty = tx >> 4, tx2 = tx & 15;
    #pragma unroll
    for (int i = 0; i < 8; ++i) {
        int t = tt + ROWI(i);
        size_t qrow = ((size_t)bh * T_ + t) * (2 * NN);
        #pragma unroll
        for (int j = 0; j < 8; j += 2) {
            int n = nn0 + COLJ(j);
            float v0 = fmaxf(acc[i][j], 0.f), v1 = fmaxf(acc[i][j+1], 0.f);
            float cs = g_cos[(size_t)t * NN + n], sn = g_sin[(size_t)t * NN + n];
            if (which == 0) {
                st_pk_pair(g_qrpk, qrow, n, v0 * cs - v1 * sn, v1 * cs + v0 * sn);
            } else {
                float qe, qo;
                ld_pk_pair(g_qrpk, qrow, n, qe, qo);
                float xe = qe * cs + qo * sn;
                float xo = qo * cs - qe * sn;
                st_pk_pair(g_xypk, qrow, n, xe * v0, xo * v1);
            }
        }
    }
#endif
}

__global__ __launch_bounds__(256) __cluster_dims__(1, 1, 1)
void k_scores_tc() {
    const int bh = blockIdx.z;
    const int ks = blockIdx.y;
    const int tt = c_pair_tt[blockIdx.x] << 7;
    const int st = c_pair_st[blockIdx.x] << 7;
    const bf16* base = g_qrpk + (size_t)bh * T_ * 8192 + (size_t)ks * 2048;
#if HAS_TC
    __shared__ __align__(1024) char sm[SM_SZ];
    uint32_t tmem = run_mma(sm, base + (size_t)tt * 8192, 8192,
                                base + (size_t)st * 8192, 8192, 32);
    const int wid = threadIdx.x >> 5, lane = threadIdx.x & 31;
    if (wid < 4) {
        float* C = g_spart + (size_t)(ks * 8 + bh) * TT_
                 + (size_t)(tt + wid * 32 + lane) * T_ + st;
        #pragma unroll
        for (int g = 0; g < 4; ++g) {
            uint32_t d[32];
            LDTM32(d, tmem + g * 32);
            TC_WAIT_LD();
            float4* p = (float4*)(C + g * 32);
            #pragma unroll
            for (int i = 0; i < 8; ++i)
                p[i] = make_float4(__uint_as_float(d[i*4]),   __uint_as_float(d[i*4+1]),
                                   __uint_as_float(d[i*4+2]), __uint_as_float(d[i*4+3]));
        }
    }
    finish_mma(sm, tmem);
#else
    float acc[8][8] = {};
    gemm128p(base + (size_t)tt * 8192, 8192, base + (size_t)st * 8192, 8192, 1024, acc);
    const int tx = threadIdx.x, ty = tx >> 4, tx2 = tx & 15;
    float* C = g_spart + (size_t)(ks * 8 + bh) * TT_;
    #pragma unroll
    for (int i = 0; i < 8; ++i) {
        float* row = C + (size_t)(tt + ROWI(i)) * T_ + st;
        *(float4*)&row[tx2 << 2]        = *(float4*)&acc[i][0];
        *(float4*)&row[64 + (tx2 << 2)] = *(float4*)&acc[i][4];
    }
#endif
}

__global__ void k_sreduce() {
    int idx = blockIdx.x * 256 + threadIdx.x;   // over BH*T*T
    int bh  = idx >> 18;
    int rem = idx & (TT_ - 1);
    int t = rem >> 9, s = rem & 511;
    float v = 0.f;
    if (s < t) {
        #pragma unroll
        for (int ks = 0; ks < 4; ++ks)
            v += g_spart[(size_t)(ks * 8 + bh) * TT_ + rem];
    }
    float hf, lf; split2(v, hf, lf);
    size_t p = ((size_t)bh * T_ + t) * 1024 + ((s >> 5) << 6) + (s & 31);
    g_spk[p]      = __float2bfloat16(hf);
    g_spk[p + 32] = __float2bfloat16(lf);
}

__global__ __launch_bounds__(256) __cluster_dims__(1, 1, 1)
void k_ykv_tc() {
    const int bh = blockIdx.z;
    const int b = bh >> 2;
    const int tt = blockIdx.y << 7, dd = blockIdx.x << 7;
    const bf16* A  = g_spk + (size_t)bh * T_ * 1024 + (size_t)tt * 1024;
    const bf16* Bm = g_xtpk + (size_t)b * D_ * 1024 + (size_t)dd * 1024;
#if HAS_TC
    __shared__ __align__(1024) char sm[SM_SZ];
    const int nchunk = (tt >> 5) + 4;          // causal: s < tt+128
    uint32_t tmem = run_mma(sm, A, 1024, Bm, 1024, nchunk);
    const int wid = threadIdx.x >> 5, lane = threadIdx.x & 31;
    if (wid < 4) {
        float* C = g_ykv + ((size_t)bh * T_ + tt + wid * 32 + lane) * D_ + dd;
        #pragma unroll
        for (int g = 0; g < 4; ++g) {
            uint32_t d[32];
            LDTM32(d, tmem + g * 32);
            TC_WAIT_LD();
            float4* p = (float4*)(C + g * 32);
            #pragma unroll
            for (int i = 0; i < 8; ++i)
                p[i] = make_float4(__uint_as_float(d[i*4]),   __uint_as_float(d[i*4+1]),
                                   __uint_as_float(d[i*4+2]), __uint_as_float(d[i*4+3]));
        }
    }
    finish_mma(sm, tmem);
#else
    float acc[8][8] = {};
    gemm128p(A, 1024, Bm, 1024, tt + 128, acc);
    const int tx = threadIdx.x, ty = tx >> 4, tx2 = tx & 15;
    #pragma unroll
    for (int i = 0; i < 8; ++i) {
        float* row = g_ykv + ((size_t)bh * T_ + tt + ROWI(i)) * D_ + dd;
        *(float4*)&row[tx2 << 2]        = *(float4*)&acc[i][0];
        *(float4*)&row[64 + (tx2 << 2)] = *(float4*)&acc[i][4];
    }
#endif
}

__global__ void k_ln_ykv() {
    size_t row = blockIdx.x;
    int d = threadIdx.x;
    float v = g_ykv[row * D_ + d];
    float mu  = blk_sum(v) * (1.0f / D_);
    float dv  = v - mu;
    float var = blk_sum(dv * dv) * (1.0f / D_);
    float r = dv / sqrtf(var + LN_EPS);
    float hf, lf; split2(r, hf, lf);
    size_t p = row * 512 + ((d >> 5) << 6) + (d & 31);
    g_ykvpk[p]      = __float2bfloat16(hf);
    g_ykvpk[p + 32] = __float2bfloat16(lf);
}

__global__ __launch_bounds__(256) __cluster_dims__(1, 1, 1)
void k_ymlp_tc() {
    const int z  = blockIdx.z;                 // bh*4 + ks
    const int bh = z >> 2, ks = z & 3;
    const int h  = bh & 3;
    const int tt = blockIdx.y << 7, dd = blockIdx.x << 7;
    const bf16* A  = g_xypk + (size_t)bh * T_ * 8192 + (size_t)tt * 8192 + (size_t)ks * 2048;
    const bf16* Bm = g_decpkt + (size_t)h * D_ * 8192 + (size_t)dd * 8192 + (size_t)ks * 2048;
#if HAS_TC
    __shared__ __align__(1024) char sm[SM_SZ];
    uint32_t tmem = run_mma(sm, A, 8192, Bm, 8192, 32);
    const int wid = threadIdx.x >> 5, lane = threadIdx.x & 31;
    if (wid < 4) {
        float* P = g_ypart + (size_t)z * T_ * D_
                 + (size_t)(tt + wid * 32 + lane) * D_ + dd;
        #pragma unroll
        for (int g = 0; g < 4; ++g) {
            uint32_t d[32];
            LDTM32(d, tmem + g * 32);
            TC_WAIT_LD();
            float4* p = (float4*)(P + g * 32);
            #pragma unroll
            for (int i = 0; i < 8; ++i)
                p[i] = make_float4(__uint_as_float(d[i*4]),   __uint_as_float(d[i*4+1]),
                                   __uint_as_float(d[i*4+2]), __uint_as_float(d[i*4+3]));
        }
    }
    finish_mma(sm, tmem);
#else
    float acc[8][8] = {};
    gemm128p(A, 8192, Bm, 8192, 1024, acc);
    const int tx = threadIdx.x, ty = tx >> 4, tx2 = tx & 15;
    float* P = g_ypart + (size_t)z * T_ * D_;
    #pragma unroll
    for (int i = 0; i < 8; ++i) {
        float* row = P + (size_t)(tt + ROWI(i)) * D_ + dd;
        *(float4*)&row[tx2 << 2]        = *(float4*)&acc[i][0];
        *(float4*)&row[64 + (tx2 << 2)] = *(float4*)&acc[i][4];
    }
#endif
}

__global__ void k_resid() {
    int bt = blockIdx.x;
    int b = bt / T_, t = bt % T_;
    int d = threadIdx.x;
    float y = 0.f;
    #pragma unroll
    for (int p = 0; p < 16; ++p)
        y += g_ypart[(((size_t)b * 16 + p) * T_ + t) * D_ + d];
    float mu1  = blk_sum(y) * (1.0f / D_);
    float yc   = y - mu1;
    float var1 = blk_sum(yc * yc) * (1.0f / D_);
    float yn   = yc / sqrtf(var1 + LN_EPS);
    float xv   = g_x[(size_t)bt * D_ + d] + yn;
    float mu2  = blk_sum(xv) * (1.0f / D_);
    float xc   = xv - mu2;
    float var2 = blk_sum(xc * xc) * (1.0f / D_);
    float r = xc / sqrtf(var2 + LN_EPS);
    g_x[(size_t)bt * D_ + d] = r;
    float hf, lf; split2(r, hf, lf);
    size_t p = (size_t)bt * 512 + ((d >> 5) << 6) + (d & 31);
    g_xpk[p]      = __float2bfloat16(hf);
    g_xpk[p + 32] = __float2bfloat16(lf);
}

// ---------------- SIMT 64x64 GEMM for logits --------------------------------
__global__ __launch_bounds__(256) void k_logits(const float* __restrict__ lmh,
                                                float* __restrict__ out) {
    __shared__ float As[16][64];
    __shared__ float Bs[16][64];
    int tt = blockIdx.y << 6, vv = blockIdx.x << 6;
    const float* Ap = g_x + (size_t)tt * D_;
    const float* Bp = lmh + vv;
    const int tx = threadIdx.x;
    const int rr = (tx >> 4) << 2;
    const int cc = (tx & 15) << 2;
    float acc[4][4] = {};
    for (int k0 = 0; k0 < D_; k0 += 16) {
        {
            int m = tx >> 2, k = (tx & 3) << 2;
            float4 v = *(const float4*)(Ap + (size_t)m * D_ + k0 + k);
            As[k+0][m] = v.x; As[k+1][m] = v.y; As[k+2][m] = v.z; As[k+3][m] = v.w;
        }
        {
            int k = tx >> 4, n = (tx & 15) << 2;
            float4 v = *(const float4*)(Bp + (size_t)(k0 + k) * V_ + n);
            Bs[k][n+0] = v.x; Bs[k][n+1] = v.y; Bs[k][n+2] = v.z; Bs[k][n+3] = v.w;
        }
        __syncthreads();
        #pragma unroll
        for (int k = 0; k < 16; ++k) {
            float4 a = *(const float4*)&As[k][rr];
            float4 b = *(const float4*)&Bs[k][cc];
            acc[0][0] += a.x*b.x; acc[0][1] += a.x*b.y; acc[0][2] += a.x*b.z; acc[0][3] += a.x*b.w;
            acc[1][0] += a.y*b.x; acc[1][1] += a.y*b.y; acc[1][2] += a.y*b.z; acc[1][3] += a.y*b.w;
            acc[2][0] += a.z*b.x; acc[2][1] += a.z*b.y; acc[2][2] += a.z*b.z; acc[2][3] += a.z*b.w;
            acc[3][0] += a.w*b.x; acc[3][1] += a.w*b.y; acc[3][2] += a.w*b.z; acc[3][3] += a.w*b.w;
        }
        __syncthreads();
    }
    #pragma unroll
    for (int i = 0; i < 4; ++i)
        #pragma unroll
        for (int j = 0; j < 4; ++j)
            out[(size_t)(tt + rr + i) * V_ + vv + cc + j] = acc[i][j];
}

__global__ void k_embed_out(float* __restrict__ out) {
    int b = blockIdx.x, d = threadIdx.x;
    float s = 0.f;
    for (int t = 0; t < T_; ++t) s += g_x[((size_t)b * T_ + t) * D_ + d];
    out[(size_t)B_ * T_ * V_ + b * D_ + d] = s * (1.0f / T_);
}

__global__ void k_trace(float* __restrict__ out) {
    int idx = blockIdx.x * 256 + threadIdx.x;   // over B*NH*NN
    int bh = idx >> 12;
    int n  = idx & (NN - 1);
    const bf16* p = g_xypk + (size_t)bh * T_ * 8192 + ((size_t)(n >> 5) << 6) + (n & 31);
    float s = 0.f;
    for (int t = 0; t < T_; ++t) {
        const bf16* q = p + (size_t)t * 8192;
        s += __bfloat162float(q[0]) + __bfloat162float(q[32]);
    }
    out[(size_t)B_ * T_ * V_ + B_ * D_ + idx] = s * (1.0f / T_);
}

// ---------------- launch ----------------------------------------------------
extern "C" void kernel_launch(void* const* d_in, const int* in_sizes, int n_in,
                              void* d_out, int out_size) {
    (void)in_sizes; (void)n_in; (void)out_size;
    const int*   ids   = (const int*)d_in[0];
    const float* table = (const float*)d_in[1];
    const float* enc   = (const float*)d_in[2];
    const float* encv  = (const float*)d_in[3];
    const float* dec   = (const float*)d_in[4];
    const float* lmh   = (const float*)d_in[5];
    float* out = (float*)d_out;

    k_tables<<<(T_ * NN) / 256, 256>>>();
    k_tpack<<<dim3(NN/32, D_/32, NH), 256>>>(enc,  0);
    k_tpack<<<dim3(NN/32, D_/32, NH), 256>>>(encv, 1);
    k_tpack<<<dim3(D_/32, NN/32, NH), 256>>>(dec,  2);
    k_embed<<<B_ * T_, 256>>>(ids, table);
    k_tpack<<<dim3(D_/32, T_/32, B_), 256>>>(nullptr, 3);

    for (int l = 0; l < N_LAYER; ++l) {
        k_enc_tc  <<<dim3(NN/128, T_/128, BH), 256>>>(0);
        k_scores_tc<<<dim3(10, 4, BH), 256>>>();
        k_sreduce <<<(BH * TT_) / 256, 256>>>();
        k_ykv_tc  <<<dim3(D_/128, T_/128, BH), 256>>>();
        k_ln_ykv  <<<BH * T_, 256>>>();
        k_enc_tc  <<<dim3(NN/128, T_/128, BH), 256>>>(1);
        k_ymlp_tc <<<dim3(D_/128, T_/128, BH * 4), 256>>>();
        k_resid   <<<B_ * T_, 256>>>();
        k_tpack<<<dim3(D_/32, T_/32, B_), 256>>>(nullptr, 3);
    }
    k_logits<<<dim3(V_/64, (B_*T_)/64), 256>>>(lmh, out);
    k_embed_out<<<B_, 256>>>(out);
    k_trace<<<(B_ * NH * NN) / 256, 256>>>(out);
}

// round 15
// speedup vs baseline: 1.0162x; 1.0162x over previous
#include <cuda_runtime.h>
#include <cuda_bf16.h>
#include <math.h>
#include <stdint.h>
#include <stddef.h>

#define N_LAYER 6
#define B_  2
#define T_  512
#define D_  256
#define NH  4
#define NN  4096
#define NH2 2048              // NN/2 compact rope table width
#define V_  256
#define BH  (B_ * NH)
#define TT_ (T_ * T_)
#define LN_EPS 1e-5f
#define TWO_PI 6.283185307179586f

typedef __nv_bfloat16 bf16;

#if defined(__CUDA_ARCH__) && (defined(__CUDA_ARCH_FEAT_SM103_ALL) || \
    defined(__CUDA_ARCH_FEAT_SM100_ALL) || defined(__CUDA_ARCH_SPECIFIC__) || \
    defined(__CUDA_ARCH_FAMILY_SPECIFIC__))
#define HAS_TC 1
#else
#define HAS_TC 0
#endif

// ---------------- scratch (device globals; no allocation allowed) ----------
__device__ __align__(256) float g_x    [B_ * T_ * D_];
__device__ __align__(256) float g_spart[4 * BH * TT_];
__device__ __align__(256) float g_ykv  [BH * T_ * D_];
__device__ __align__(256) float g_ypart[BH * 4 * T_ * D_];
__device__ __align__(256) float g_cos  [T_ * NH2];           // compact: per even/odd pair
__device__ __align__(256) float g_sin  [T_ * NH2];
// packed bf16 hi/lo planes: row layout = per 32-k chunk [hi0..31 | lo0..31]
__device__ __align__(256) bf16 g_xpk   [B_ * T_ * 2 * D_];
__device__ __align__(256) bf16 g_xtpk  [B_ * D_ * 2 * T_];
__device__ __align__(256) bf16 g_xspk  [BH * T_ * 2 * NN];   // x_sparse (packed)
__device__ __align__(256) bf16 g_qrpk  [BH * T_ * 2 * NN];
__device__ __align__(256) bf16 g_spk   [BH * T_ * 2 * T_];
__device__ __align__(256) bf16 g_ykvpk [BH * T_ * 2 * D_];
__device__ __align__(256) bf16 g_xypk  [BH * T_ * 2 * NN];   // xy_sparse (packed)
__device__ __align__(256) bf16 g_encpkt [NH * NN * 2 * D_];
__device__ __align__(256) bf16 g_encvpkt[NH * NN * 2 * D_];
__device__ __align__(256) bf16 g_decpkt [NH * D_ * 2 * NN];

__constant__ int c_pair_tt[10] = {0,1,1,2,2,2,3,3,3,3};
__constant__ int c_pair_st[10] = {0,0,1,0,1,2,0,1,2,3};

__device__ __forceinline__ float blk_sum(float v) {
    __shared__ float sh[8];
    #pragma unroll
    for (int o = 16; o > 0; o >>= 1) v += __shfl_xor_sync(0xffffffffu, v, o);
    __syncthreads();
    if ((threadIdx.x & 31) == 0) sh[threadIdx.x >> 5] = v;
    __syncthreads();
    float t = 0.f;
    #pragma unroll
    for (int i = 0; i < 8; ++i) t += sh[i];
    return t;
}

__device__ __forceinline__ uint32_t pack2(float a, float b) {
    __nv_bfloat162 t = __floats2bfloat162_rn(a, b);
    return *reinterpret_cast<uint32_t*>(&t);
}
__device__ __forceinline__ void split2(float v, float& hf, float& lf) {
    __nv_bfloat16 h = __float2bfloat16(v);
    hf = __bfloat162float(h);
    lf = v - hf;
}

#define ROWI(i) ((ty << 2) + ((i) & 3) + (((i) >> 2) << 6))
#define COLJ(j) ((tx2 << 2) + ((j) & 3) + (((j) >> 2) << 6))

__device__ __forceinline__ void st_pk_pair(bf16* __restrict__ dst, size_t rowbase,
                                           int n, float v0, float v1) {
    size_t p = rowbase + (((size_t)(n >> 5)) << 6) + (n & 31);
    float h0, l0, h1, l1;
    split2(v0, h0, l0); split2(v1, h1, l1);
    dst[p]      = __float2bfloat16(h0);
    dst[p + 1]  = __float2bfloat16(h1);
    dst[p + 32] = __float2bfloat16(l0);
    dst[p + 33] = __float2bfloat16(l1);
}

__device__ __forceinline__ void ld_pk_pair(const bf16* __restrict__ src, size_t rowbase,
                                           int n, float& v0, float& v1) {
    size_t p = rowbase + (((size_t)(n >> 5)) << 6) + (n & 31);
    v0 = __bfloat162float(src[p])     + __bfloat162float(src[p + 32]);
    v1 = __bfloat162float(src[p + 1]) + __bfloat162float(src[p + 33]);
}

#if HAS_TC
// =================== tcgen05 path ===========================================
__device__ __forceinline__ uint32_t smem_u32(const void* p) {
    return (uint32_t)__cvta_generic_to_shared(p);
}
__device__ __forceinline__ uint32_t elect1() {
    uint32_t pred;
    asm volatile("{\n\t.reg .pred p;\n\telect.sync _|p, 0xFFFFFFFF;\n\t"
                 "selp.b32 %0, 1, 0, p;\n\t}" : "=r"(pred));
    return pred;
}

#define SWZ(off) ((off) ^ (((off) >> 3) & 0x70))

#define MBAR_INIT(a, n) \
    asm volatile("mbarrier.init.shared.b64 [%0], %1;" :: "r"(a), "r"(n) : "memory")
#define MBAR_INVAL(a) \
    asm volatile("mbarrier.inval.shared.b64 [%0];" :: "r"(a) : "memory")
#define MBAR_WAIT(a, ph) do {                                                  \
    asm volatile("{\n\t.reg .pred P1;\n\t"                                     \
        "WL_%=:\n\t"                                                           \
        "mbarrier.try_wait.parity.acquire.cta.shared::cta.b64 P1, [%0], %1, 0x989680;\n\t" \
        "@P1 bra.uni WD_%=;\n\t"                                               \
        "bra.uni WL_%=;\n\t"                                                   \
        "WD_%=:\n\t}" :: "r"(a), "r"(ph) : "memory");                          \
} while (0)

#define TC_ALLOC(sa, n) \
    asm volatile("tcgen05.alloc.cta_group::1.sync.aligned.shared::cta.b32 [%0], %1;" \
                 :: "r"(sa), "r"(n) : "memory")
#define TC_RELINQ() \
    asm volatile("tcgen05.relinquish_alloc_permit.cta_group::1.sync.aligned;")
#define TC_DEALLOC(t, n) \
    asm volatile("tcgen05.dealloc.cta_group::1.sync.aligned.b32 %0, %1;" :: "r"(t), "r"(n))
#define TC_COMMIT(a) \
    asm volatile("tcgen05.commit.cta_group::1.mbarrier::arrive::one.shared::cluster.b64 [%0];" \
                 :: "r"(a) : "memory")
#define TC_FENCE_AFTER()  asm volatile("tcgen05.fence::after_thread_sync;" ::: "memory")
#define TC_FENCE_BEFORE() asm volatile("tcgen05.fence::before_thread_sync;" ::: "memory")
#define FENCE_ASYNC() asm volatile("fence.proxy.async.shared::cta;" ::: "memory")
#define TC_WAIT_LD() asm volatile("tcgen05.wait::ld.sync.aligned;" ::: "memory")

#define LDTM32(r, addr)                                                        \
    asm volatile("tcgen05.ld.sync.aligned.32x32b.x32.b32 "                     \
        "{%0,%1,%2,%3,%4,%5,%6,%7,%8,%9,%10,%11,%12,%13,%14,%15,"             \
        "%16,%17,%18,%19,%20,%21,%22,%23,%24,%25,%26,%27,%28,%29,%30,%31},[%32];" \
        : "=r"((r)[0]),"=r"((r)[1]),"=r"((r)[2]),"=r"((r)[3]),                \
          "=r"((r)[4]),"=r"((r)[5]),"=r"((r)[6]),"=r"((r)[7]),                \
          "=r"((r)[8]),"=r"((r)[9]),"=r"((r)[10]),"=r"((r)[11]),              \
          "=r"((r)[12]),"=r"((r)[13]),"=r"((r)[14]),"=r"((r)[15]),            \
          "=r"((r)[16]),"=r"((r)[17]),"=r"((r)[18]),"=r"((r)[19]),            \
          "=r"((r)[20]),"=r"((r)[21]),"=r"((r)[22]),"=r"((r)[23]),            \
          "=r"((r)[24]),"=r"((r)[25]),"=r"((r)[26]),"=r"((r)[27]),            \
          "=r"((r)[28]),"=r"((r)[29]),"=r"((r)[30]),"=r"((r)[31])             \
        : "r"(addr))

static __device__ __forceinline__ uint64_t mk_desc(uint32_t addr) {
    return ((uint64_t)2 << 61) | ((uint64_t)1 << 46) | ((uint64_t)64 << 32)
         | ((uint64_t)1 << 16) | (uint64_t)((addr >> 4) & 0x3FFF);
}

#define IDESC_F16 0x08200490u   // dtype=F32, a/b=BF16, N=128, M=128

__device__ __forceinline__ void mma_ss(uint32_t d, uint64_t ad, uint64_t bd, uint32_t en) {
    asm volatile("{\n\t.reg .pred p;\n\tsetp.ne.u32 p,%4,0;\n\t"
        "tcgen05.mma.cta_group::1.kind::f16 [%0], %1, %2, %3, {%5,%5,%5,%5}, p;\n\t}"
        :: "r"(d), "l"(ad), "l"(bd), "r"(IDESC_F16), "r"(en), "r"(0u) : "memory");
}

#define SM_TM  0
#define SM_BAR 8
#define SM_A   1024
#define SM_B   (1024 + 16384)
#define SM_SZ  (1024 + 32768)

// D = A * B^T, 128x128 fp32 tile; 3-term bf16 split; serial per chunk (R9).
__device__ uint32_t run_mma(char* sm, const bf16* __restrict__ A, size_t lda,
                            const bf16* __restrict__ Bm, size_t ldb, int nchunk) {
    const uint32_t sb = smem_u32(sm);
    const int tid = threadIdx.x, wid = tid >> 5;
    if (tid == 0) MBAR_INIT(sb + SM_BAR, 1);
    if (wid == 0) TC_ALLOC(sb + SM_TM, 128);
    __syncthreads();
    uint32_t tmem;
    asm volatile("ld.shared.b32 %0, [%1];" : "=r"(tmem) : "r"(sb + SM_TM));
    const uint64_t adesc = mk_desc(sb + SM_A);
    const uint64_t bdesc = mk_desc(sb + SM_B);

    const int row  = tid >> 1;
    const int half = (tid & 1) << 6;
    const char* gA = (const char*)(A + (size_t)row * lda) + half;
    const char* gB = (const char*)(Bm + (size_t)row * ldb) + half;
    char* sA[4]; char* sBp[4];
    #pragma unroll
    for (int i = 0; i < 4; ++i) {
        int off = row * 128 + half + i * 16;
        sA[i]  = sm + SM_A + SWZ(off);
        sBp[i] = sm + SM_B + SWZ(off);
    }

    for (int c = 0; c < nchunk; ++c) {
        #pragma unroll
        for (int i = 0; i < 4; ++i) {
            *(uint4*)sA[i]  = *(const uint4*)(gA + (size_t)c * 128 + i * 16);
            *(uint4*)sBp[i] = *(const uint4*)(gB + (size_t)c * 128 + i * 16);
        }
        __syncthreads();
        if (wid == 0 && elect1()) {
            FENCE_ASYNC();
            mma_ss(tmem, adesc + 0, bdesc + 0, c != 0);
            mma_ss(tmem, adesc + 2, bdesc + 2, 1);
            mma_ss(tmem, adesc + 0, bdesc + 4, 1);
            mma_ss(tmem, adesc + 2, bdesc + 6, 1);
            mma_ss(tmem, adesc + 4, bdesc + 0, 1);
            mma_ss(tmem, adesc + 6, bdesc + 2, 1);
            TC_COMMIT(sb + SM_BAR);
        }
        MBAR_WAIT(sb + SM_BAR, c & 1);
        __syncthreads();
    }
    TC_FENCE_AFTER();
    return tmem;
}

__device__ __forceinline__ void finish_mma(char* sm, uint32_t tmem) {
    TC_FENCE_BEFORE();
    __syncthreads();
    const uint32_t sb = smem_u32(sm);
    if (threadIdx.x == 0) MBAR_INVAL(sb + SM_BAR);
    if ((threadIdx.x >> 5) == 0) {
        TC_RELINQ();
        TC_DEALLOC(tmem, 128);
    }
}
#else
// =================== SIMT fallback path =====================================
__device__ __forceinline__ float4 ldpk4(const bf16* __restrict__ rowp, int k) {
    const bf16* p = rowp + ((k >> 5) << 6) + (k & 31);
    uint2 h = *(const uint2*)p;
    uint2 l = *(const uint2*)(p + 32);
    float2 fh0 = __bfloat1622float2(*(__nv_bfloat162*)&h.x);
    float2 fh1 = __bfloat1622float2(*(__nv_bfloat162*)&h.y);
    float2 fl0 = __bfloat1622float2(*(__nv_bfloat162*)&l.x);
    float2 fl1 = __bfloat1622float2(*(__nv_bfloat162*)&l.y);
    return make_float4(fh0.x + fl0.x, fh0.y + fl0.y, fh1.x + fl1.x, fh1.y + fl1.y);
}

__device__ void gemm128p(const bf16* __restrict__ A, int lda,
                         const bf16* __restrict__ B, int ldb,
                         int K, float acc[8][8]) {
    __shared__ float As[16][128];
    __shared__ float Bs[16][128];
    const int tx  = threadIdx.x;
    const int ty  = tx >> 4;
    const int tx2 = tx & 15;
    const int am = tx >> 2;
    const int ak = (tx & 3) << 2;
    for (int k0 = 0; k0 < K; k0 += 16) {
        float4 a0 = ldpk4(A + (size_t)am * lda, k0 + ak);
        float4 a1 = ldpk4(A + (size_t)(am + 64) * lda, k0 + ak);
        float4 b0 = ldpk4(B + (size_t)am * ldb, k0 + ak);
        float4 b1 = ldpk4(B + (size_t)(am + 64) * ldb, k0 + ak);
        As[ak+0][am] = a0.x; As[ak+1][am] = a0.y; As[ak+2][am] = a0.z; As[ak+3][am] = a0.w;
        As[ak+0][am+64] = a1.x; As[ak+1][am+64] = a1.y; As[ak+2][am+64] = a1.z; As[ak+3][am+64] = a1.w;
        Bs[ak+0][am] = b0.x; Bs[ak+1][am] = b0.y; Bs[ak+2][am] = b0.z; Bs[ak+3][am] = b0.w;
        Bs[ak+0][am+64] = b1.x; Bs[ak+1][am+64] = b1.y; Bs[ak+2][am+64] = b1.z; Bs[ak+3][am+64] = b1.w;
        __syncthreads();
        #pragma unroll
        for (int k = 0; k < 16; ++k) {
            float4 va0 = *(const float4*)&As[k][ty << 2];
            float4 va1 = *(const float4*)&As[k][64 + (ty << 2)];
            float4 vb0 = *(const float4*)&Bs[k][tx2 << 2];
            float4 vb1 = *(const float4*)&Bs[k][64 + (tx2 << 2)];
            float av[8] = {va0.x, va0.y, va0.z, va0.w, va1.x, va1.y, va1.z, va1.w};
            float bv[8] = {vb0.x, vb0.y, vb0.z, vb0.w, vb1.x, vb1.y, vb1.z, vb1.w};
            #pragma unroll
            for (int i = 0; i < 8; ++i)
                #pragma unroll
                for (int j = 0; j < 8; ++j)
                    acc[i][j] += av[i] * bv[j];
        }
        __syncthreads();
    }
}
#endif  // HAS_TC

// ---------------- elementwise / setup kernels -------------------------------
__global__ void k_tables() {               // compact: one entry per even/odd pair
    int idx = blockIdx.x * 256 + threadIdx.x;   // over T * NN/2
    int t  = idx >> 11;
    int n2 = idx & (NH2 - 1);
    float qidx = (float)(n2 << 1);
    float e = qidx / (float)NN;
    float freq = 1.0f / powf(65536.0f, e) / TWO_PI;
    float phase = (float)t * freq;
    float ph = (phase - floorf(phase)) * TWO_PI;
    float s, c;
    sincosf(ph, &s, &c);
    g_cos[idx] = c;
    g_sin[idx] = s;
}

__global__ void k_tpack(const float* __restrict__ ext, int mode) {
    __shared__ float tile[32][33];
    const float* src; bf16* dst; int lds, ldd; size_t ss, ds;
    if (mode == 0)      { src = ext; dst = g_encpkt;  lds = NN; ldd = 512;  ss = (size_t)D_*NN; ds = (size_t)NN*512; }
    else if (mode == 1) { src = ext; dst = g_encvpkt; lds = NN; ldd = 512;  ss = (size_t)D_*NN; ds = (size_t)NN*512; }
    else if (mode == 2) { src = ext; dst = g_decpkt;  lds = D_; ldd = 8192; ss = (size_t)NN*D_; ds = (size_t)D_*8192; }
    else                { src = g_x; dst = g_xtpk;    lds = D_; ldd = 1024; ss = (size_t)T_*D_; ds = (size_t)D_*1024; }
    src += (size_t)blockIdx.z * ss;
    dst += (size_t)blockIdx.z * ds;
    int c0 = blockIdx.x << 5, r0 = blockIdx.y << 5;
    int tx = threadIdx.x & 31, ty = threadIdx.x >> 5;
    #pragma unroll
    for (int i = 0; i < 4; ++i) {
        int r = r0 + ty + (i << 3);
        tile[ty + (i << 3)][tx] = src[(size_t)r * lds + c0 + tx];
    }
    __syncthreads();
    #pragma unroll
    for (int i = 0; i < 4; ++i) {
        int c = c0 + ty + (i << 3);
        float v = tile[tx][ty + (i << 3)];
        float hf, lf; split2(v, hf, lf);
        size_t base = (size_t)c * ldd + ((size_t)(r0 >> 5) << 6) + tx;
        dst[base]      = __float2bfloat16(hf);
        dst[base + 32] = __float2bfloat16(lf);
    }
}

__global__ void k_embed(const int* __restrict__ ids, const float* __restrict__ table) {
    int bt = blockIdx.x;
    int d  = threadIdx.x;
    float v = table[(size_t)ids[bt] * D_ + d];
    float mu  = blk_sum(v) * (1.0f / D_);
    float dv  = v - mu;
    float var = blk_sum(dv * dv) * (1.0f / D_);
    float r = dv / sqrtf(var + LN_EPS);
    g_x[(size_t)bt * D_ + d] = r;
    float hf, lf; split2(r, hf, lf);
    size_t p = (size_t)bt * 512 + ((d >> 5) << 6) + (d & 31);
    g_xpk[p]      = __float2bfloat16(hf);
    g_xpk[p + 32] = __float2bfloat16(lf);
}

// ---------------- main GEMM kernels -----------------------------------------
__global__ __launch_bounds__(256) __cluster_dims__(1, 1, 1)
void k_enc_tc(int which) {   // 0 = encoder (xspk + rope->qrpk), 1 = encoder_v (xypk)
    const int bh = blockIdx.z;
    const int b = bh >> 2, h = bh & 3;
    const int tt = blockIdx.y << 7, nn0 = blockIdx.x << 7;
    const bf16* A = which ? g_ykvpk + (size_t)bh * T_ * 512 + (size_t)tt * 512
                          : g_xpk + (size_t)b * T_ * 512 + (size_t)tt * 512;
    const bf16* Bw = (which ? g_encvpkt : g_encpkt) + (size_t)h * NN * 512 + (size_t)nn0 * 512;
#if HAS_TC
    __shared__ __align__(1024) char sm[SM_SZ];
    uint32_t tmem = run_mma(sm, A, 512, Bw, 512, 8);
    const int wid = threadIdx.x >> 5, lane = threadIdx.x & 31;
    if (wid < 4) {
        const int t = tt + wid * 32 + lane;
        const size_t qrow = ((size_t)bh * T_ + t) * (2 * NN) + ((size_t)(nn0 >> 5) << 6);
        #pragma unroll
        for (int g = 0; g < 4; ++g) {
            uint32_t d[32];
            LDTM32(d, tmem + g * 32);
            TC_WAIT_LD();
            float v[32];
            #pragma unroll
            for (int j = 0; j < 32; ++j) v[j] = fmaxf(__uint_as_float(d[j]), 0.f);
            uint32_t whi[16], wlo[16];
            if (which == 0) {
                // pack xs
                #pragma unroll
                for (int j = 0; j < 32; j += 2) {
                    float h0, l0, h1, l1;
                    split2(v[j], h0, l0); split2(v[j+1], h1, l1);
                    whi[j >> 1] = pack2(h0, h1);
                    wlo[j >> 1] = pack2(l0, l1);
                }
                uint4* xp = (uint4*)&g_xspk[qrow + g * 64];
                #pragma unroll
                for (int i = 0; i < 4; ++i)
                    xp[i] = make_uint4(whi[i*4], whi[i*4+1], whi[i*4+2], whi[i*4+3]);
                #pragma unroll
                for (int i = 0; i < 4; ++i)
                    xp[4 + i] = make_uint4(wlo[i*4], wlo[i*4+1], wlo[i*4+2], wlo[i*4+3]);
                // rope + pack qr (compact tables: one entry per pair)
                const float* crow = g_cos + (size_t)t * NH2 + ((nn0 + g * 32) >> 1);
                const float* srow = g_sin + (size_t)t * NH2 + ((nn0 + g * 32) >> 1);
                #pragma unroll
                for (int j = 0; j < 32; j += 2) {
                    float cs = crow[j >> 1], sn = srow[j >> 1];
                    float qe = v[j] * cs - v[j+1] * sn;
                    float qo = v[j+1] * cs + v[j] * sn;
                    float he, le, ho, lo2;
                    split2(qe, he, le); split2(qo, ho, lo2);
                    whi[j >> 1] = pack2(he, ho);
                    wlo[j >> 1] = pack2(le, lo2);
                }
                uint4* qp = (uint4*)&g_qrpk[qrow + g * 64];
                #pragma unroll
                for (int i = 0; i < 4; ++i)
                    qp[i] = make_uint4(whi[i*4], whi[i*4+1], whi[i*4+2], whi[i*4+3]);
                #pragma unroll
                for (int i = 0; i < 4; ++i)
                    qp[4 + i] = make_uint4(wlo[i*4], wlo[i*4+1], wlo[i*4+2], wlo[i*4+3]);
            } else {
                // xy = xs * relu(acc): read packed xs, write packed xy
                const uint4* xp = (const uint4*)&g_xspk[qrow + g * 64];
                #pragma unroll
                for (int i = 0; i < 4; ++i) {
                    uint4 hh = xp[i], ll = xp[4 + i];
                    uint32_t hw[4] = {hh.x, hh.y, hh.z, hh.w};
                    uint32_t lw[4] = {ll.x, ll.y, ll.z, ll.w};
                    #pragma unroll
                    for (int q = 0; q < 4; ++q) {
                        float2 fh = __bfloat1622float2(*(__nv_bfloat162*)&hw[q]);
                        float2 fl = __bfloat1622float2(*(__nv_bfloat162*)&lw[q]);
                        int j = (i * 4 + q) * 2;
                        v[j]   = (fh.x + fl.x) * v[j];
                        v[j+1] = (fh.y + fl.y) * v[j+1];
                    }
                }
                #pragma unroll
                for (int j = 0; j < 32; j += 2) {
                    float h0, l0, h1, l1;
                    split2(v[j], h0, l0); split2(v[j+1], h1, l1);
                    whi[j >> 1] = pack2(h0, h1);
                    wlo[j >> 1] = pack2(l0, l1);
                }
                uint4* qp = (uint4*)&g_xypk[qrow + g * 64];
                #pragma unroll
                for (int i = 0; i < 4; ++i)
                    qp[i] = make_uint4(whi[i*4], whi[i*4+1], whi[i*4+2], whi[i*4+3]);
                #pragma unroll
                for (int i = 0; i < 4; ++i)
                    qp[4 + i] = make_uint4(wlo[i*4], wlo[i*4+1], wlo[i*4+2], wlo[i*4+3]);
            }
        }
    }
    finish_mma(sm, tmem);
#else
    float acc[8][8] = {};
    gemm128p(A, 512, Bw, 512, D_, acc);
    const int tx = threadIdx.x, ty = tx >> 4, tx2 = tx & 15;
    #pragma unroll
    for (int i = 0; i < 8; ++i) {
        int t = tt + ROWI(i);
        size_t qrow = ((size_t)bh * T_ + t) * (2 * NN);
        #pragma unroll
        for (int j = 0; j < 8; j += 2) {
            int n = nn0 + COLJ(j);
            float v0 = fmaxf(acc[i][j], 0.f), v1 = fmaxf(acc[i][j+1], 0.f);
            if (which == 0) {
                st_pk_pair(g_xspk, qrow, n, v0, v1);
                float cs = g_cos[(size_t)t * NH2 + (n >> 1)];
                float sn = g_sin[(size_t)t * NH2 + (n >> 1)];
                st_pk_pair(g_qrpk, qrow, n, v0 * cs - v1 * sn, v1 * cs + v0 * sn);
            } else {
                float x0, x1;
                ld_pk_pair(g_xspk, qrow, n, x0, x1);
                st_pk_pair(g_xypk, qrow, n, x0 * v0, x1 * v1);
            }
        }
    }
#endif
}

__global__ __launch_bounds__(256) __cluster_dims__(1, 1, 1)
void k_scores_tc() {
    const int bh = blockIdx.z;
    const int ks = blockIdx.y;
    const int tt = c_pair_tt[blockIdx.x] << 7;
    const int st = c_pair_st[blockIdx.x] << 7;
    const bf16* base = g_qrpk + (size_t)bh * T_ * 8192 + (size_t)ks * 2048;
#if HAS_TC
    __shared__ __align__(1024) char sm[SM_SZ];
    uint32_t tmem = run_mma(sm, base + (size_t)tt * 8192, 8192,
                                base + (size_t)st * 8192, 8192, 32);
    const int wid = threadIdx.x >> 5, lane = threadIdx.x & 31;
    if (wid < 4) {
        float* C = g_spart + (size_t)(ks * 8 + bh) * TT_
                 + (size_t)(tt + wid * 32 + lane) * T_ + st;
        #pragma unroll
        for (int g = 0; g < 4; ++g) {
            uint32_t d[32];
            LDTM32(d, tmem + g * 32);
            TC_WAIT_LD();
            float4* p = (float4*)(C + g * 32);
            #pragma unroll
            for (int i = 0; i < 8; ++i)
                p[i] = make_float4(__uint_as_float(d[i*4]),   __uint_as_float(d[i*4+1]),
                                   __uint_as_float(d[i*4+2]), __uint_as_float(d[i*4+3]));
        }
    }
    finish_mma(sm, tmem);
#else
    float acc[8][8] = {};
    gemm128p(base + (size_t)tt * 8192, 8192, base + (size_t)st * 8192, 8192, 1024, acc);
    const int tx = threadIdx.x, ty = tx >> 4, tx2 = tx & 15;
    float* C = g_spart + (size_t)(ks * 8 + bh) * TT_;
    #pragma unroll
    for (int i = 0; i < 8; ++i) {
        float* row = C + (size_t)(tt + ROWI(i)) * T_ + st;
        *(float4*)&row[tx2 << 2]        = *(float4*)&acc[i][0];
        *(float4*)&row[64 + (tx2 << 2)] = *(float4*)&acc[i][4];
    }
#endif
}

__global__ void k_sreduce() {
    int idx = blockIdx.x * 256 + threadIdx.x;   // over BH*T*T
    int bh  = idx >> 18;
    int rem = idx & (TT_ - 1);
    int t = rem >> 9, s = rem & 511;
    float v = 0.f;
    if (s < t) {
        #pragma unroll
        for (int ks = 0; ks < 4; ++ks)
            v += g_spart[(size_t)(ks * 8 + bh) * TT_ + rem];
    }
    float hf, lf; split2(v, hf, lf);
    size_t p = ((size_t)bh * T_ + t) * 1024 + ((s >> 5) << 6) + (s & 31);
    g_spk[p]      = __float2bfloat16(hf);
    g_spk[p + 32] = __float2bfloat16(lf);
}

__global__ __launch_bounds__(256) __cluster_dims__(1, 1, 1)
void k_ykv_tc() {
    const int bh = blockIdx.z;
    const int b = bh >> 2;
    const int tt = blockIdx.y << 7, dd = blockIdx.x << 7;
    const bf16* A  = g_spk + (size_t)bh * T_ * 1024 + (size_t)tt * 1024;
    const bf16* Bm = g_xtpk + (size_t)b * D_ * 1024 + (size_t)dd * 1024;
#if HAS_TC
    __shared__ __align__(1024) char sm[SM_SZ];
    const int nchunk = (tt >> 5) + 4;          // causal: s < tt+128
    uint32_t tmem = run_mma(sm, A, 1024, Bm, 1024, nchunk);
    const int wid = threadIdx.x >> 5, lane = threadIdx.x & 31;
    if (wid < 4) {
        float* C = g_ykv + ((size_t)bh * T_ + tt + wid * 32 + lane) * D_ + dd;
        #pragma unroll
        for (int g = 0; g < 4; ++g) {
            uint32_t d[32];
            LDTM32(d, tmem + g * 32);
            TC_WAIT_LD();
            float4* p = (float4*)(C + g * 32);
            #pragma unroll
            for (int i = 0; i < 8; ++i)
                p[i] = make_float4(__uint_as_float(d[i*4]),   __uint_as_float(d[i*4+1]),
                                   __uint_as_float(d[i*4+2]), __uint_as_float(d[i*4+3]));
        }
    }
    finish_mma(sm, tmem);
#else
    float acc[8][8] = {};
    gemm128p(A, 1024, Bm, 1024, tt + 128, acc);
    const int tx = threadIdx.x, ty = tx >> 4, tx2 = tx & 15;
    #pragma unroll
    for (int i = 0; i < 8; ++i) {
        float* row = g_ykv + ((size_t)bh * T_ + tt + ROWI(i)) * D_ + dd;
        *(float4*)&row[tx2 << 2]        = *(float4*)&acc[i][0];
        *(float4*)&row[64 + (tx2 << 2)] = *(float4*)&acc[i][4];
    }
#endif
}

__global__ void k_ln_ykv() {
    size_t row = blockIdx.x;
    int d = threadIdx.x;
    float v = g_ykv[row * D_ + d];
    float mu  = blk_sum(v) * (1.0f / D_);
    float dv  = v - mu;
    float var = blk_sum(dv * dv) * (1.0f / D_);
    float r = dv / sqrtf(var + LN_EPS);
    float hf, lf; split2(r, hf, lf);
    size_t p = row * 512 + ((d >> 5) << 6) + (d & 31);
    g_ykvpk[p]      = __float2bfloat16(hf);
    g_ykvpk[p + 32] = __float2bfloat16(lf);
}

__global__ __launch_bounds__(256) __cluster_dims__(1, 1, 1)
void k_ymlp_tc() {
    const int z  = blockIdx.z;                 // bh*4 + ks
    const int bh = z >> 2, ks = z & 3;
    const int h  = bh & 3;
    const int tt = blockIdx.y << 7, dd = blockIdx.x << 7;
    const bf16* A  = g_xypk + (size_t)bh * T_ * 8192 + (size_t)tt * 8192 + (size_t)ks * 2048;
    const bf16* Bm = g_decpkt + (size_t)h * D_ * 8192 + (size_t)dd * 8192 + (size_t)ks * 2048;
#if HAS_TC
    __shared__ __align__(1024) char sm[SM_SZ];
    uint32_t tmem = run_mma(sm, A, 8192, Bm, 8192, 32);
    const int wid = threadIdx.x >> 5, lane = threadIdx.x & 31;
    if (wid < 4) {
        float* P = g_ypart + (size_t)z * T_ * D_
                 + (size_t)(tt + wid * 32 + lane) * D_ + dd;
        #pragma unroll
        for (int g = 0; g < 4; ++g) {
            uint32_t d[32];
            LDTM32(d, tmem + g * 32);
            TC_WAIT_LD();
            float4* p = (float4*)(P + g * 32);
            #pragma unroll
            for (int i = 0; i < 8; ++i)
                p[i] = make_float4(__uint_as_float(d[i*4]),   __uint_as_float(d[i*4+1]),
                                   __uint_as_float(d[i*4+2]), __uint_as_float(d[i*4+3]));
        }
    }
    finish_mma(sm, tmem);
#else
    float acc[8][8] = {};
    gemm128p(A, 8192, Bm, 8192, 1024, acc);
    const int tx = threadIdx.x, ty = tx >> 4, tx2 = tx & 15;
    float* P = g_ypart + (size_t)z * T_ * D_;
    #pragma unroll
    for (int i = 0; i < 8; ++i) {
        float* row = P + (size_t)(tt + ROWI(i)) * D_ + dd;
        *(float4*)&row[tx2 << 2]        = *(float4*)&acc[i][0];
        *(float4*)&row[64 + (tx2 << 2)] = *(float4*)&acc[i][4];
    }
#endif
}

__global__ void k_resid() {
    int bt = blockIdx.x;
    int b = bt / T_, t = bt % T_;
    int d = threadIdx.x;
    float y = 0.f;
    #pragma unroll
    for (int p = 0; p < 16; ++p)
        y += g_ypart[(((size_t)b * 16 + p) * T_ + t) * D_ + d];
    float mu1  = blk_sum(y) * (1.0f / D_);
    float yc   = y - mu1;
    float var1 = blk_sum(yc * yc) * (1.0f / D_);
    float yn   = yc / sqrtf(var1 + LN_EPS);
    float xv   = g_x[(size_t)bt * D_ + d] + yn;
    float mu2  = blk_sum(xv) * (1.0f / D_);
    float xc   = xv - mu2;
    float var2 = blk_sum(xc * xc) * (1.0f / D_);
    float r = xc / sqrtf(var2 + LN_EPS);
    g_x[(size_t)bt * D_ + d] = r;
    float hf, lf; split2(r, hf, lf);
    size_t p = (size_t)bt * 512 + ((d >> 5) << 6) + (d & 31);
    g_xpk[p]      = __float2bfloat16(hf);
    g_xpk[p + 32] = __float2bfloat16(lf);
}

// ---------------- SIMT 64x64 GEMM for logits --------------------------------
__global__ __launch_bounds__(256) void k_logits(const float* __restrict__ lmh,
                                                float* __restrict__ out) {
    __shared__ float As[16][64];
    __shared__ float Bs[16][64];
    int tt = blockIdx.y << 6, vv = blockIdx.x << 6;
    const float* Ap = g_x + (size_t)tt * D_;
    const float* Bp = lmh + vv;
    const int tx = threadIdx.x;
    const int rr = (tx >> 4) << 2;
    const int cc = (tx & 15) << 2;
    float acc[4][4] = {};
    for (int k0 = 0; k0 < D_; k0 += 16) {
        {
            int m = tx >> 2, k = (tx & 3) << 2;
            float4 v = *(const float4*)(Ap + (size_t)m * D_ + k0 + k);
            As[k+0][m] = v.x; As[k+1][m] = v.y; As[k+2][m] = v.z; As[k+3][m] = v.w;
        }
        {
            int k = tx >> 4, n = (tx & 15) << 2;
            float4 v = *(const float4*)(Bp + (size_t)(k0 + k) * V_ + n);
            Bs[k][n+0] = v.x; Bs[k][n+1] = v.y; Bs[k][n+2] = v.z; Bs[k][n+3] = v.w;
        }
        __syncthreads();
        #pragma unroll
        for (int k = 0; k < 16; ++k) {
            float4 a = *(const float4*)&As[k][rr];
            float4 b = *(const float4*)&Bs[k][cc];
            acc[0][0] += a.x*b.x; acc[0][1] += a.x*b.y; acc[0][2] += a.x*b.z; acc[0][3] += a.x*b.w;
            acc[1][0] += a.y*b.x; acc[1][1] += a.y*b.y; acc[1][2] += a.y*b.z; acc[1][3] += a.y*b.w;
            acc[2][0] += a.z*b.x; acc[2][1] += a.z*b.y; acc[2][2] += a.z*b.z; acc[2][3] += a.z*b.w;
            acc[3][0] += a.w*b.x; acc[3][1] += a.w*b.y; acc[3][2] += a.w*b.z; acc[3][3] += a.w*b.w;
        }
        __syncthreads();
    }
    #pragma unroll
    for (int i = 0; i < 4; ++i)
        #pragma unroll
        for (int j = 0; j < 4; ++j)
            out[(size_t)(tt + rr + i) * V_ + vv + cc + j] = acc[i][j];
}

__global__ void k_embed_out(float* __restrict__ out) {
    int b = blockIdx.x, d = threadIdx.x;
    float s = 0.f;
    for (int t = 0; t < T_; ++t) s += g_x[((size_t)b * T_ + t) * D_ + d];
    out[(size_t)B_ * T_ * V_ + b * D_ + d] = s * (1.0f / T_);
}

__global__ void k_trace(float* __restrict__ out) {
    int idx = blockIdx.x * 256 + threadIdx.x;   // over B*NH*NN
    int bh = idx >> 12;
    int n  = idx & (NN - 1);
    const bf16* p = g_xypk + (size_t)bh * T_ * 8192 + ((size_t)(n >> 5) << 6) + (n & 31);
    float s = 0.f;
    for (int t = 0; t < T_; ++t) {
        const bf16* q = p + (size_t)t * 8192;
        s += __bfloat162float(q[0]) + __bfloat162float(q[32]);
    }
    out[(size_t)B_ * T_ * V_ + B_ * D_ + idx] = s * (1.0f / T_);
}

// ---------------- launch ----------------------------------------------------
extern "C" void kernel_launch(void* const* d_in, const int* in_sizes, int n_in,
                              void* d_out, int out_size) {
    (void)in_sizes; (void)n_in; (void)out_size;
    const int*   ids   = (const int*)d_in[0];
    const float* table = (const float*)d_in[1];
    const float* enc   = (const float*)d_in[2];
    const float* encv  = (const float*)d_in[3];
    const float* dec   = (const float*)d_in[4];
    const float* lmh   = (const float*)d_in[5];
    float* out = (float*)d_out;

    k_tables<<<(T_ * NH2) / 256, 256>>>();
    k_tpack<<<dim3(NN/32, D_/32, NH), 256>>>(enc,  0);
    k_tpack<<<dim3(NN/32, D_/32, NH), 256>>>(encv, 1);
    k_tpack<<<dim3(D_/32, NN/32, NH), 256>>>(dec,  2);
    k_embed<<<B_ * T_, 256>>>(ids, table);
    k_tpack<<<dim3(D_/32, T_/32, B_), 256>>>(nullptr, 3);

    for (int l = 0; l < N_LAYER; ++l) {
        k_enc_tc  <<<dim3(NN/128, T_/128, BH), 256>>>(0);
        k_scores_tc<<<dim3(10, 4, BH), 256>>>();
        k_sreduce <<<(BH * TT_) / 256, 256>>>();
        k_ykv_tc  <<<dim3(D_/128, T_/128, BH), 256>>>();
        k_ln_ykv  <<<BH * T_, 256>>>();
        k_enc_tc  <<<dim3(NN/128, T_/128, BH), 256>>>(1);
        k_ymlp_tc <<<dim3(D_/128, T_/128, BH * 4), 256>>>();
        k_resid   <<<B_ * T_, 256>>>();
        k_tpack<<<dim3(D_/32, T_/32, B_), 256>>>(nullptr, 3);
    }
    k_logits<<<dim3(V_/64, (B_*T_)/64), 256>>>(lmh, out);
    k_embed_out<<<B_, 256>>>(out);
    k_trace<<<(B_ * NH * NN) / 256, 256>>>(out);
}

// round 16
// speedup vs baseline: 1.0348x; 1.0183x over previous
#include <cuda_runtime.h>
#include <cuda_bf16.h>
#include <math.h>
#include <stdint.h>
#include <stddef.h>

#define N_LAYER 6
#define B_  2
#define T_  512
#define D_  256
#define NH  4
#define NN  4096
#define NH2 2048              // NN/2 compact rope table width
#define V_  256
#define BH  (B_ * NH)
#define TT_ (T_ * T_)
#define LN_EPS 1e-5f
#define TWO_PI 6.283185307179586f

typedef __nv_bfloat16 bf16;

#if defined(__CUDA_ARCH__) && (defined(__CUDA_ARCH_FEAT_SM103_ALL) || \
    defined(__CUDA_ARCH_FEAT_SM100_ALL) || defined(__CUDA_ARCH_SPECIFIC__) || \
    defined(__CUDA_ARCH_FAMILY_SPECIFIC__))
#define HAS_TC 1
#else
#define HAS_TC 0
#endif

// ---------------- scratch (device globals; no allocation allowed) ----------
__device__ __align__(256) float g_x    [B_ * T_ * D_];
__device__ __align__(256) float g_spart[4 * BH * TT_];
__device__ __align__(256) float g_ykv  [BH * T_ * D_];
__device__ __align__(256) float g_ypart[BH * 4 * T_ * D_];
__device__ __align__(256) float g_cos  [T_ * NH2];           // compact: per even/odd pair
__device__ __align__(256) float g_sin  [T_ * NH2];
// packed bf16 hi/lo planes: row layout = per 32-k chunk [hi0..31 | lo0..31]
__device__ __align__(256) bf16 g_xpk   [B_ * T_ * 2 * D_];
__device__ __align__(256) bf16 g_xtpk  [B_ * D_ * 2 * T_];
__device__ __align__(256) bf16 g_xspk  [BH * T_ * 2 * NN];   // x_sparse (packed)
__device__ __align__(256) bf16 g_qrpk  [BH * T_ * 2 * NN];
__device__ __align__(256) bf16 g_spk   [BH * T_ * 2 * T_];
__device__ __align__(256) bf16 g_ykvpk [BH * T_ * 2 * D_];
__device__ __align__(256) bf16 g_xypk  [BH * T_ * 2 * NN];   // xy_sparse (packed)
__device__ __align__(256) bf16 g_encpkt [NH * NN * 2 * D_];
__device__ __align__(256) bf16 g_encvpkt[NH * NN * 2 * D_];
__device__ __align__(256) bf16 g_decpkt [NH * D_ * 2 * NN];

__constant__ int c_pair_tt[10] = {0,1,1,2,2,2,3,3,3,3};
__constant__ int c_pair_st[10] = {0,0,1,0,1,2,0,1,2,3};

__device__ __forceinline__ float blk_sum(float v) {
    __shared__ float sh[8];
    #pragma unroll
    for (int o = 16; o > 0; o >>= 1) v += __shfl_xor_sync(0xffffffffu, v, o);
    __syncthreads();
    if ((threadIdx.x & 31) == 0) sh[threadIdx.x >> 5] = v;
    __syncthreads();
    float t = 0.f;
    #pragma unroll
    for (int i = 0; i < 8; ++i) t += sh[i];
    return t;
}

__device__ __forceinline__ uint32_t pack2(float a, float b) {
    __nv_bfloat162 t = __floats2bfloat162_rn(a, b);
    return *reinterpret_cast<uint32_t*>(&t);
}
__device__ __forceinline__ void split2(float v, float& hf, float& lf) {
    __nv_bfloat16 h = __float2bfloat16(v);
    hf = __bfloat162float(h);
    lf = v - hf;
}

#define ROWI(i) ((ty << 2) + ((i) & 3) + (((i) >> 2) << 6))
#define COLJ(j) ((tx2 << 2) + ((j) & 3) + (((j) >> 2) << 6))

__device__ __forceinline__ void st_pk_pair(bf16* __restrict__ dst, size_t rowbase,
                                           int n, float v0, float v1) {
    size_t p = rowbase + (((size_t)(n >> 5)) << 6) + (n & 31);
    float h0, l0, h1, l1;
    split2(v0, h0, l0); split2(v1, h1, l1);
    dst[p]      = __float2bfloat16(h0);
    dst[p + 1]  = __float2bfloat16(h1);
    dst[p + 32] = __float2bfloat16(l0);
    dst[p + 33] = __float2bfloat16(l1);
}

__device__ __forceinline__ void ld_pk_pair(const bf16* __restrict__ src, size_t rowbase,
                                           int n, float& v0, float& v1) {
    size_t p = rowbase + (((size_t)(n >> 5)) << 6) + (n & 31);
    v0 = __bfloat162float(src[p])     + __bfloat162float(src[p + 32]);
    v1 = __bfloat162float(src[p + 1]) + __bfloat162float(src[p + 33]);
}

#if HAS_TC
// =================== tcgen05 path ===========================================
__device__ __forceinline__ uint32_t smem_u32(const void* p) {
    return (uint32_t)__cvta_generic_to_shared(p);
}
__device__ __forceinline__ uint32_t elect1() {
    uint32_t pred;
    asm volatile("{\n\t.reg .pred p;\n\telect.sync _|p, 0xFFFFFFFF;\n\t"
                 "selp.b32 %0, 1, 0, p;\n\t}" : "=r"(pred));
    return pred;
}

#define SWZ(off) ((off) ^ (((off) >> 3) & 0x70))

#define MBAR_INIT(a, n) \
    asm volatile("mbarrier.init.shared.b64 [%0], %1;" :: "r"(a), "r"(n) : "memory")
#define MBAR_INVAL(a) \
    asm volatile("mbarrier.inval.shared.b64 [%0];" :: "r"(a) : "memory")
#define MBAR_WAIT(a, ph) do {                                                  \
    asm volatile("{\n\t.reg .pred P1;\n\t"                                     \
        "WL_%=:\n\t"                                                           \
        "mbarrier.try_wait.parity.acquire.cta.shared::cta.b64 P1, [%0], %1, 0x989680;\n\t" \
        "@P1 bra.uni WD_%=;\n\t"                                               \
        "bra.uni WL_%=;\n\t"                                                   \
        "WD_%=:\n\t}" :: "r"(a), "r"(ph) : "memory");                          \
} while (0)

#define TC_ALLOC(sa, n) \
    asm volatile("tcgen05.alloc.cta_group::1.sync.aligned.shared::cta.b32 [%0], %1;" \
                 :: "r"(sa), "r"(n) : "memory")
#define TC_RELINQ() \
    asm volatile("tcgen05.relinquish_alloc_permit.cta_group::1.sync.aligned;")
#define TC_DEALLOC(t, n) \
    asm volatile("tcgen05.dealloc.cta_group::1.sync.aligned.b32 %0, %1;" :: "r"(t), "r"(n))
#define TC_COMMIT(a) \
    asm volatile("tcgen05.commit.cta_group::1.mbarrier::arrive::one.shared::cluster.b64 [%0];" \
                 :: "r"(a) : "memory")
#define TC_FENCE_AFTER()  asm volatile("tcgen05.fence::after_thread_sync;" ::: "memory")
#define TC_FENCE_BEFORE() asm volatile("tcgen05.fence::before_thread_sync;" ::: "memory")
#define FENCE_ASYNC() asm volatile("fence.proxy.async.shared::cta;" ::: "memory")
#define TC_WAIT_LD() asm volatile("tcgen05.wait::ld.sync.aligned;" ::: "memory")

#define LDTM32(r, addr)                                                        \
    asm volatile("tcgen05.ld.sync.aligned.32x32b.x32.b32 "                     \
        "{%0,%1,%2,%3,%4,%5,%6,%7,%8,%9,%10,%11,%12,%13,%14,%15,"             \
        "%16,%17,%18,%19,%20,%21,%22,%23,%24,%25,%26,%27,%28,%29,%30,%31},[%32];" \
        : "=r"((r)[0]),"=r"((r)[1]),"=r"((r)[2]),"=r"((r)[3]),                \
          "=r"((r)[4]),"=r"((r)[5]),"=r"((r)[6]),"=r"((r)[7]),                \
          "=r"((r)[8]),"=r"((r)[9]),"=r"((r)[10]),"=r"((r)[11]),              \
          "=r"((r)[12]),"=r"((r)[13]),"=r"((r)[14]),"=r"((r)[15]),            \
          "=r"((r)[16]),"=r"((r)[17]),"=r"((r)[18]),"=r"((r)[19]),            \
          "=r"((r)[20]),"=r"((r)[21]),"=r"((r)[22]),"=r"((r)[23]),            \
          "=r"((r)[24]),"=r"((r)[25]),"=r"((r)[26]),"=r"((r)[27]),            \
          "=r"((r)[28]),"=r"((r)[29]),"=r"((r)[30]),"=r"((r)[31])             \
        : "r"(addr))

static __device__ __forceinline__ uint64_t mk_desc(uint32_t addr) {
    return ((uint64_t)2 << 61) | ((uint64_t)1 << 46) | ((uint64_t)64 << 32)
         | ((uint64_t)1 << 16) | (uint64_t)((addr >> 4) & 0x3FFF);
}

#define IDESC_F16 0x08200490u   // dtype=F32, a/b=BF16, N=128, M=128

__device__ __forceinline__ void mma_ss(uint32_t d, uint64_t ad, uint64_t bd, uint32_t en) {
    asm volatile("{\n\t.reg .pred p;\n\tsetp.ne.u32 p,%4,0;\n\t"
        "tcgen05.mma.cta_group::1.kind::f16 [%0], %1, %2, %3, {%5,%5,%5,%5}, p;\n\t}"
        :: "r"(d), "l"(ad), "l"(bd), "r"(IDESC_F16), "r"(en), "r"(0u) : "memory");
}

#define SM_TM  0
#define SM_BAR 8
#define SM_A   1024
#define SM_B   (1024 + 16384)
#define SM_SZ  (1024 + 32768)

// D = A * B^T, 128x128 fp32 tile; 3-term bf16 split; serial per chunk (R9).
__device__ uint32_t run_mma(char* sm, const bf16* __restrict__ A, size_t lda,
                            const bf16* __restrict__ Bm, size_t ldb, int nchunk) {
    const uint32_t sb = smem_u32(sm);
    const int tid = threadIdx.x, wid = tid >> 5;
    if (tid == 0) MBAR_INIT(sb + SM_BAR, 1);
    if (wid == 0) TC_ALLOC(sb + SM_TM, 128);
    __syncthreads();
    uint32_t tmem;
    asm volatile("ld.shared.b32 %0, [%1];" : "=r"(tmem) : "r"(sb + SM_TM));
    const uint64_t adesc = mk_desc(sb + SM_A);
    const uint64_t bdesc = mk_desc(sb + SM_B);

    const int row  = tid >> 1;
    const int half = (tid & 1) << 6;
    const char* gA = (const char*)(A + (size_t)row * lda) + half;
    const char* gB = (const char*)(Bm + (size_t)row * ldb) + half;
    char* sA[4]; char* sBp[4];
    #pragma unroll
    for (int i = 0; i < 4; ++i) {
        int off = row * 128 + half + i * 16;
        sA[i]  = sm + SM_A + SWZ(off);
        sBp[i] = sm + SM_B + SWZ(off);
    }

    for (int c = 0; c < nchunk; ++c) {
        #pragma unroll
        for (int i = 0; i < 4; ++i) {
            *(uint4*)sA[i]  = *(const uint4*)(gA + (size_t)c * 128 + i * 16);
            *(uint4*)sBp[i] = *(const uint4*)(gB + (size_t)c * 128 + i * 16);
        }
        __syncthreads();
        if (wid == 0 && elect1()) {
            FENCE_ASYNC();
            mma_ss(tmem, adesc + 0, bdesc + 0, c != 0);
            mma_ss(tmem, adesc + 2, bdesc + 2, 1);
            mma_ss(tmem, adesc + 0, bdesc + 4, 1);
            mma_ss(tmem, adesc + 2, bdesc + 6, 1);
            mma_ss(tmem, adesc + 4, bdesc + 0, 1);
            mma_ss(tmem, adesc + 6, bdesc + 2, 1);
            TC_COMMIT(sb + SM_BAR);
        }
        MBAR_WAIT(sb + SM_BAR, c & 1);
        __syncthreads();
    }
    TC_FENCE_AFTER();
    return tmem;
}

__device__ __forceinline__ void finish_mma(char* sm, uint32_t tmem) {
    TC_FENCE_BEFORE();
    __syncthreads();
    const uint32_t sb = smem_u32(sm);
    if (threadIdx.x == 0) MBAR_INVAL(sb + SM_BAR);
    if ((threadIdx.x >> 5) == 0) {
        TC_RELINQ();
        TC_DEALLOC(tmem, 128);
    }
}
#else
// =================== SIMT fallback path =====================================
__device__ __forceinline__ float4 ldpk4(const bf16* __restrict__ rowp, int k) {
    const bf16* p = rowp + ((k >> 5) << 6) + (k & 31);
    uint2 h = *(const uint2*)p;
    uint2 l = *(const uint2*)(p + 32);
    float2 fh0 = __bfloat1622float2(*(__nv_bfloat162*)&h.x);
    float2 fh1 = __bfloat1622float2(*(__nv_bfloat162*)&h.y);
    float2 fl0 = __bfloat1622float2(*(__nv_bfloat162*)&l.x);
    float2 fl1 = __bfloat1622float2(*(__nv_bfloat162*)&l.y);
    return make_float4(fh0.x + fl0.x, fh0.y + fl0.y, fh1.x + fl1.x, fh1.y + fl1.y);
}

__device__ void gemm128p(const bf16* __restrict__ A, int lda,
                         const bf16* __restrict__ B, int ldb,
                         int K, float acc[8][8]) {
    __shared__ float As[16][128];
    __shared__ float Bs[16][128];
    const int tx  = threadIdx.x;
    const int ty  = tx >> 4;
    const int tx2 = tx & 15;
    const int am = tx >> 2;
    const int ak = (tx & 3) << 2;
    for (int k0 = 0; k0 < K; k0 += 16) {
        float4 a0 = ldpk4(A + (size_t)am * lda, k0 + ak);
        float4 a1 = ldpk4(A + (size_t)(am + 64) * lda, k0 + ak);
        float4 b0 = ldpk4(B + (size_t)am * ldb, k0 + ak);
        float4 b1 = ldpk4(B + (size_t)(am + 64) * ldb, k0 + ak);
        As[ak+0][am] = a0.x; As[ak+1][am] = a0.y; As[ak+2][am] = a0.z; As[ak+3][am] = a0.w;
        As[ak+0][am+64] = a1.x; As[ak+1][am+64] = a1.y; As[ak+2][am+64] = a1.z; As[ak+3][am+64] = a1.w;
        Bs[ak+0][am] = b0.x; Bs[ak+1][am] = b0.y; Bs[ak+2][am] = b0.z; Bs[ak+3][am] = b0.w;
        Bs[ak+0][am+64] = b1.x; Bs[ak+1][am+64] = b1.y; Bs[ak+2][am+64] = b1.z; Bs[ak+3][am+64] = b1.w;
        __syncthreads();
        #pragma unroll
        for (int k = 0; k < 16; ++k) {
            float4 va0 = *(const float4*)&As[k][ty << 2];
            float4 va1 = *(const float4*)&As[k][64 + (ty << 2)];
            float4 vb0 = *(const float4*)&Bs[k][tx2 << 2];
            float4 vb1 = *(const float4*)&Bs[k][64 + (tx2 << 2)];
            float av[8] = {va0.x, va0.y, va0.z, va0.w, va1.x, va1.y, va1.z, va1.w};
            float bv[8] = {vb0.x, vb0.y, vb0.z, vb0.w, vb1.x, vb1.y, vb1.z, vb1.w};
            #pragma unroll
            for (int i = 0; i < 8; ++i)
                #pragma unroll
                for (int j = 0; j < 8; ++j)
                    acc[i][j] += av[i] * bv[j];
        }
        __syncthreads();
    }
}
#endif  // HAS_TC

// ---------------- elementwise / setup kernels -------------------------------
__global__ void k_tables() {               // compact: one entry per even/odd pair
    int idx = blockIdx.x * 256 + threadIdx.x;   // over T * NN/2
    int t  = idx >> 11;
    int n2 = idx & (NH2 - 1);
    float qidx = (float)(n2 << 1);
    float e = qidx / (float)NN;
    float freq = 1.0f / powf(65536.0f, e) / TWO_PI;
    float phase = (float)t * freq;
    float ph = (phase - floorf(phase)) * TWO_PI;
    float s, c;
    sincosf(ph, &s, &c);
    g_cos[idx] = c;
    g_sin[idx] = s;
}

__global__ void k_zero_spk() {             // once per launch: upper blocks stay 0
    size_t i = (size_t)blockIdx.x * 256 + threadIdx.x;   // uint4 units
    ((uint4*)g_spk)[i] = make_uint4(0, 0, 0, 0);
}

__global__ void k_tpack(const float* __restrict__ ext, int mode) {
    __shared__ float tile[32][33];
    const float* src; bf16* dst; int lds, ldd; size_t ss, ds;
    if (mode == 0)      { src = ext; dst = g_encpkt;  lds = NN; ldd = 512;  ss = (size_t)D_*NN; ds = (size_t)NN*512; }
    else if (mode == 1) { src = ext; dst = g_encvpkt; lds = NN; ldd = 512;  ss = (size_t)D_*NN; ds = (size_t)NN*512; }
    else if (mode == 2) { src = ext; dst = g_decpkt;  lds = D_; ldd = 8192; ss = (size_t)NN*D_; ds = (size_t)D_*8192; }
    else                { src = g_x; dst = g_xtpk;    lds = D_; ldd = 1024; ss = (size_t)T_*D_; ds = (size_t)D_*1024; }
    src += (size_t)blockIdx.z * ss;
    dst += (size_t)blockIdx.z * ds;
    int c0 = blockIdx.x << 5, r0 = blockIdx.y << 5;
    int tx = threadIdx.x & 31, ty = threadIdx.x >> 5;
    #pragma unroll
    for (int i = 0; i < 4; ++i) {
        int r = r0 + ty + (i << 3);
        tile[ty + (i << 3)][tx] = src[(size_t)r * lds + c0 + tx];
    }
    __syncthreads();
    #pragma unroll
    for (int i = 0; i < 4; ++i) {
        int c = c0 + ty + (i << 3);
        float v = tile[tx][ty + (i << 3)];
        float hf, lf; split2(v, hf, lf);
        size_t base = (size_t)c * ldd + ((size_t)(r0 >> 5) << 6) + tx;
        dst[base]      = __float2bfloat16(hf);
        dst[base + 32] = __float2bfloat16(lf);
    }
}

__global__ void k_embed(const int* __restrict__ ids, const float* __restrict__ table) {
    int bt = blockIdx.x;
    int d  = threadIdx.x;
    float v = table[(size_t)ids[bt] * D_ + d];
    float mu  = blk_sum(v) * (1.0f / D_);
    float dv  = v - mu;
    float var = blk_sum(dv * dv) * (1.0f / D_);
    float r = dv / sqrtf(var + LN_EPS);
    g_x[(size_t)bt * D_ + d] = r;
    float hf, lf; split2(r, hf, lf);
    size_t p = (size_t)bt * 512 + ((d >> 5) << 6) + (d & 31);
    g_xpk[p]      = __float2bfloat16(hf);
    g_xpk[p + 32] = __float2bfloat16(lf);
}

// ---------------- main GEMM kernels -----------------------------------------
__global__ __launch_bounds__(256) __cluster_dims__(1, 1, 1)
void k_enc_tc(int which) {   // 0 = encoder (xspk + rope->qrpk), 1 = encoder_v (xypk)
    const int bh = blockIdx.z;
    const int b = bh >> 2, h = bh & 3;
    const int tt = blockIdx.y << 7, nn0 = blockIdx.x << 7;
    const bf16* A = which ? g_ykvpk + (size_t)bh * T_ * 512 + (size_t)tt * 512
                          : g_xpk + (size_t)b * T_ * 512 + (size_t)tt * 512;
    const bf16* Bw = (which ? g_encvpkt : g_encpkt) + (size_t)h * NN * 512 + (size_t)nn0 * 512;
#if HAS_TC
    __shared__ __align__(1024) char sm[SM_SZ];
    uint32_t tmem = run_mma(sm, A, 512, Bw, 512, 8);
    const int wid = threadIdx.x >> 5, lane = threadIdx.x & 31;
    if (wid < 4) {
        const int t = tt + wid * 32 + lane;
        const size_t qrow = ((size_t)bh * T_ + t) * (2 * NN) + ((size_t)(nn0 >> 5) << 6);
        #pragma unroll
        for (int g = 0; g < 4; ++g) {
            uint32_t d[32];
            LDTM32(d, tmem + g * 32);
            TC_WAIT_LD();
            float v[32];
            #pragma unroll
            for (int j = 0; j < 32; ++j) v[j] = fmaxf(__uint_as_float(d[j]), 0.f);
            uint32_t whi[16], wlo[16];
            if (which == 0) {
                // pack xs
                #pragma unroll
                for (int j = 0; j < 32; j += 2) {
                    float h0, l0, h1, l1;
                    split2(v[j], h0, l0); split2(v[j+1], h1, l1);
                    whi[j >> 1] = pack2(h0, h1);
                    wlo[j >> 1] = pack2(l0, l1);
                }
                uint4* xp = (uint4*)&g_xspk[qrow + g * 64];
                #pragma unroll
                for (int i = 0; i < 4; ++i)
                    xp[i] = make_uint4(whi[i*4], whi[i*4+1], whi[i*4+2], whi[i*4+3]);
                #pragma unroll
                for (int i = 0; i < 4; ++i)
                    xp[4 + i] = make_uint4(wlo[i*4], wlo[i*4+1], wlo[i*4+2], wlo[i*4+3]);
                // rope + pack qr (compact tables: one entry per pair)
                const float* crow = g_cos + (size_t)t * NH2 + ((nn0 + g * 32) >> 1);
                const float* srow = g_sin + (size_t)t * NH2 + ((nn0 + g * 32) >> 1);
                #pragma unroll
                for (int j = 0; j < 32; j += 2) {
                    float cs = crow[j >> 1], sn = srow[j >> 1];
                    float qe = v[j] * cs - v[j+1] * sn;
                    float qo = v[j+1] * cs + v[j] * sn;
                    float he, le, ho, lo2;
                    split2(qe, he, le); split2(qo, ho, lo2);
                    whi[j >> 1] = pack2(he, ho);
                    wlo[j >> 1] = pack2(le, lo2);
                }
                uint4* qp = (uint4*)&g_qrpk[qrow + g * 64];
                #pragma unroll
                for (int i = 0; i < 4; ++i)
                    qp[i] = make_uint4(whi[i*4], whi[i*4+1], whi[i*4+2], whi[i*4+3]);
                #pragma unroll
                for (int i = 0; i < 4; ++i)
                    qp[4 + i] = make_uint4(wlo[i*4], wlo[i*4+1], wlo[i*4+2], wlo[i*4+3]);
            } else {
                // xy = xs * relu(acc): read packed xs, write packed xy
                const uint4* xp = (const uint4*)&g_xspk[qrow + g * 64];
                #pragma unroll
                for (int i = 0; i < 4; ++i) {
                    uint4 hh = xp[i], ll = xp[4 + i];
                    uint32_t hw[4] = {hh.x, hh.y, hh.z, hh.w};
                    uint32_t lw[4] = {ll.x, ll.y, ll.z, ll.w};
                    #pragma unroll
                    for (int q = 0; q < 4; ++q) {
                        float2 fh = __bfloat1622float2(*(__nv_bfloat162*)&hw[q]);
                        float2 fl = __bfloat1622float2(*(__nv_bfloat162*)&lw[q]);
                        int j = (i * 4 + q) * 2;
                        v[j]   = (fh.x + fl.x) * v[j];
                        v[j+1] = (fh.y + fl.y) * v[j+1];
                    }
                }
                #pragma unroll
                for (int j = 0; j < 32; j += 2) {
                    float h0, l0, h1, l1;
                    split2(v[j], h0, l0); split2(v[j+1], h1, l1);
                    whi[j >> 1] = pack2(h0, h1);
                    wlo[j >> 1] = pack2(l0, l1);
                }
                uint4* qp = (uint4*)&g_xypk[qrow + g * 64];
                #pragma unroll
                for (int i = 0; i < 4; ++i)
                    qp[i] = make_uint4(whi[i*4], whi[i*4+1], whi[i*4+2], whi[i*4+3]);
                #pragma unroll
                for (int i = 0; i < 4; ++i)
                    qp[4 + i] = make_uint4(wlo[i*4], wlo[i*4+1], wlo[i*4+2], wlo[i*4+3]);
            }
        }
    }
    finish_mma(sm, tmem);
#else
    float acc[8][8] = {};
    gemm128p(A, 512, Bw, 512, D_, acc);
    const int tx = threadIdx.x, ty = tx >> 4, tx2 = tx & 15;
    #pragma unroll
    for (int i = 0; i < 8; ++i) {
        int t = tt + ROWI(i);
        size_t qrow = ((size_t)bh * T_ + t) * (2 * NN);
        #pragma unroll
        for (int j = 0; j < 8; j += 2) {
            int n = nn0 + COLJ(j);
            float v0 = fmaxf(acc[i][j], 0.f), v1 = fmaxf(acc[i][j+1], 0.f);
            if (which == 0) {
                st_pk_pair(g_xspk, qrow, n, v0, v1);
                float cs = g_cos[(size_t)t * NH2 + (n >> 1)];
                float sn = g_sin[(size_t)t * NH2 + (n >> 1)];
                st_pk_pair(g_qrpk, qrow, n, v0 * cs - v1 * sn, v1 * cs + v0 * sn);
            } else {
                float x0, x1;
                ld_pk_pair(g_xspk, qrow, n, x0, x1);
                st_pk_pair(g_xypk, qrow, n, x0 * v0, x1 * v1);
            }
        }
    }
#endif
}

__global__ __launch_bounds__(256) __cluster_dims__(1, 1, 1)
void k_scores_tc() {
    const int bh = blockIdx.z;
    const int ks = blockIdx.y;
    const int tt = c_pair_tt[blockIdx.x] << 7;
    const int st = c_pair_st[blockIdx.x] << 7;
    const bf16* base = g_qrpk + (size_t)bh * T_ * 8192 + (size_t)ks * 2048;
#if HAS_TC
    __shared__ __align__(1024) char sm[SM_SZ];
    uint32_t tmem = run_mma(sm, base + (size_t)tt * 8192, 8192,
                                base + (size_t)st * 8192, 8192, 32);
    const int wid = threadIdx.x >> 5, lane = threadIdx.x & 31;
    if (wid < 4) {
        float* C = g_spart + (size_t)(ks * 8 + bh) * TT_
                 + (size_t)(tt + wid * 32 + lane) * T_ + st;
        #pragma unroll
        for (int g = 0; g < 4; ++g) {
            uint32_t d[32];
            LDTM32(d, tmem + g * 32);
            TC_WAIT_LD();
            float4* p = (float4*)(C + g * 32);
            #pragma unroll
            for (int i = 0; i < 8; ++i)
                p[i] = make_float4(__uint_as_float(d[i*4]),   __uint_as_float(d[i*4+1]),
                                   __uint_as_float(d[i*4+2]), __uint_as_float(d[i*4+3]));
        }
    }
    finish_mma(sm, tmem);
#else
    float acc[8][8] = {};
    gemm128p(base + (size_t)tt * 8192, 8192, base + (size_t)st * 8192, 8192, 1024, acc);
    const int tx = threadIdx.x, ty = tx >> 4, tx2 = tx & 15;
    float* C = g_spart + (size_t)(ks * 8 + bh) * TT_;
    #pragma unroll
    for (int i = 0; i < 8; ++i) {
        float* row = C + (size_t)(tt + ROWI(i)) * T_ + st;
        *(float4*)&row[tx2 << 2]        = *(float4*)&acc[i][0];
        *(float4*)&row[64 + (tx2 << 2)] = *(float4*)&acc[i][4];
    }
#endif
}

// causal-pairs-only, float4-vectorized reduction of spart -> packed spk.
// grid: (16, 10, BH); 256 threads, 4 elems/thread covering one 128x128 tile.
__global__ void k_sreduce() {
    const int bh = blockIdx.z;
    const int bt = c_pair_tt[blockIdx.y], bs = c_pair_st[blockIdx.y];
    int e  = blockIdx.x * 1024 + threadIdx.x * 4;   // elem within tile
    int r  = e >> 7;                                 // row 0..127
    int cq = e & 127;                                // col, multiple of 4
    int t = (bt << 7) + r;
    int s = (bs << 7) + cq;
    size_t rem = (size_t)t * T_ + s;
    float4 v = make_float4(0.f, 0.f, 0.f, 0.f);
    #pragma unroll
    for (int ks = 0; ks < 4; ++ks) {
        float4 q = *(const float4*)&g_spart[(size_t)(ks * 8 + bh) * TT_ + rem];
        v.x += q.x; v.y += q.y; v.z += q.z; v.w += q.w;
    }
    if (s + 0 >= t) v.x = 0.f;
    if (s + 1 >= t) v.y = 0.f;
    if (s + 2 >= t) v.z = 0.f;
    if (s + 3 >= t) v.w = 0.f;
    size_t rowbase = ((size_t)bh * T_ + t) * 1024;
    st_pk_pair(g_spk, rowbase, s,     v.x, v.y);
    st_pk_pair(g_spk, rowbase, s + 2, v.z, v.w);
}

__global__ __launch_bounds__(256) __cluster_dims__(1, 1, 1)
void k_ykv_tc() {
    const int bh = blockIdx.z;
    const int b = bh >> 2;
    const int tt = blockIdx.y << 7, dd = blockIdx.x << 7;
    const bf16* A  = g_spk + (size_t)bh * T_ * 1024 + (size_t)tt * 1024;
    const bf16* Bm = g_xtpk + (size_t)b * D_ * 1024 + (size_t)dd * 1024;
#if HAS_TC
    __shared__ __align__(1024) char sm[SM_SZ];
    const int nchunk = (tt >> 5) + 4;          // causal: s < tt+128
    uint32_t tmem = run_mma(sm, A, 1024, Bm, 1024, nchunk);
    const int wid = threadIdx.x >> 5, lane = threadIdx.x & 31;
    if (wid < 4) {
        float* C = g_ykv + ((size_t)bh * T_ + tt + wid * 32 + lane) * D_ + dd;
        #pragma unroll
        for (int g = 0; g < 4; ++g) {
            uint32_t d[32];
            LDTM32(d, tmem + g * 32);
            TC_WAIT_LD();
            float4* p = (float4*)(C + g * 32);
            #pragma unroll
            for (int i = 0; i < 8; ++i)
                p[i] = make_float4(__uint_as_float(d[i*4]),   __uint_as_float(d[i*4+1]),
                                   __uint_as_float(d[i*4+2]), __uint_as_float(d[i*4+3]));
        }
    }
    finish_mma(sm, tmem);
#else
    float acc[8][8] = {};
    gemm128p(A, 1024, Bm, 1024, tt + 128, acc);
    const int tx = threadIdx.x, ty = tx >> 4, tx2 = tx & 15;
    #pragma unroll
    for (int i = 0; i < 8; ++i) {
        float* row = g_ykv + ((size_t)bh * T_ + tt + ROWI(i)) * D_ + dd;
        *(float4*)&row[tx2 << 2]        = *(float4*)&acc[i][0];
        *(float4*)&row[64 + (tx2 << 2)] = *(float4*)&acc[i][4];
    }
#endif
}

__global__ void k_ln_ykv() {
    size_t row = blockIdx.x;
    int d = threadIdx.x;
    float v = g_ykv[row * D_ + d];
    float mu  = blk_sum(v) * (1.0f / D_);
    float dv  = v - mu;
    float var = blk_sum(dv * dv) * (1.0f / D_);
    float r = dv / sqrtf(var + LN_EPS);
    float hf, lf; split2(r, hf, lf);
    size_t p = row * 512 + ((d >> 5) << 6) + (d & 31);
    g_ykvpk[p]      = __float2bfloat16(hf);
    g_ykvpk[p + 32] = __float2bfloat16(lf);
}

__global__ __launch_bounds__(256) __cluster_dims__(1, 1, 1)
void k_ymlp_tc() {
    const int z  = blockIdx.z;                 // bh*4 + ks
    const int bh = z >> 2, ks = z & 3;
    const int h  = bh & 3;
    const int tt = blockIdx.y << 7, dd = blockIdx.x << 7;
    const bf16* A  = g_xypk + (size_t)bh * T_ * 8192 + (size_t)tt * 8192 + (size_t)ks * 2048;
    const bf16* Bm = g_decpkt + (size_t)h * D_ * 8192 + (size_t)dd * 8192 + (size_t)ks * 2048;
#if HAS_TC
    __shared__ __align__(1024) char sm[SM_SZ];
    uint32_t tmem = run_mma(sm, A, 8192, Bm, 8192, 32);
    const int wid = threadIdx.x >> 5, lane = threadIdx.x & 31;
    if (wid < 4) {
        float* P = g_ypart + (size_t)z * T_ * D_
                 + (size_t)(tt + wid * 32 + lane) * D_ + dd;
        #pragma unroll
        for (int g = 0; g < 4; ++g) {
            uint32_t d[32];
            LDTM32(d, tmem + g * 32);
            TC_WAIT_LD();
            float4* p = (float4*)(P + g * 32);
            #pragma unroll
            for (int i = 0; i < 8; ++i)
                p[i] = make_float4(__uint_as_float(d[i*4]),   __uint_as_float(d[i*4+1]),
                                   __uint_as_float(d[i*4+2]), __uint_as_float(d[i*4+3]));
        }
    }
    finish_mma(sm, tmem);
#else
    float acc[8][8] = {};
    gemm128p(A, 8192, Bm, 8192, 1024, acc);
    const int tx = threadIdx.x, ty = tx >> 4, tx2 = tx & 15;
    float* P = g_ypart + (size_t)z * T_ * D_;
    #pragma unroll
    for (int i = 0; i < 8; ++i) {
        float* row = P + (size_t)(tt + ROWI(i)) * D_ + dd;
        *(float4*)&row[tx2 << 2]        = *(float4*)&acc[i][0];
        *(float4*)&row[64 + (tx2 << 2)] = *(float4*)&acc[i][4];
    }
#endif
}

__global__ void k_resid() {
    int bt = blockIdx.x;
    int b = bt / T_, t = bt % T_;
    int d = threadIdx.x;
    float y = 0.f;
    #pragma unroll
    for (int p = 0; p < 16; ++p)
        y += g_ypart[(((size_t)b * 16 + p) * T_ + t) * D_ + d];
    float mu1  = blk_sum(y) * (1.0f / D_);
    float yc   = y - mu1;
    float var1 = blk_sum(yc * yc) * (1.0f / D_);
    float yn   = yc / sqrtf(var1 + LN_EPS);
    float xv   = g_x[(size_t)bt * D_ + d] + yn;
    float mu2  = blk_sum(xv) * (1.0f / D_);
    float xc   = xv - mu2;
    float var2 = blk_sum(xc * xc) * (1.0f / D_);
    float r = xc / sqrtf(var2 + LN_EPS);
    g_x[(size_t)bt * D_ + d] = r;
    float hf, lf; split2(r, hf, lf);
    size_t p = (size_t)bt * 512 + ((d >> 5) << 6) + (d & 31);
    g_xpk[p]      = __float2bfloat16(hf);
    g_xpk[p + 32] = __float2bfloat16(lf);
}

// ---------------- SIMT 64x64 GEMM for logits --------------------------------
__global__ __launch_bounds__(256) void k_logits(const float* __restrict__ lmh,
                                                float* __restrict__ out) {
    __shared__ float As[16][64];
    __shared__ float Bs[16][64];
    int tt = blockIdx.y << 6, vv = blockIdx.x << 6;
    const float* Ap = g_x + (size_t)tt * D_;
    const float* Bp = lmh + vv;
    const int tx = threadIdx.x;
    const int rr = (tx >> 4) << 2;
    const int cc = (tx & 15) << 2;
    float acc[4][4] = {};
    for (int k0 = 0; k0 < D_; k0 += 16) {
        {
            int m = tx >> 2, k = (tx & 3) << 2;
            float4 v = *(const float4*)(Ap + (size_t)m * D_ + k0 + k);
            As[k+0][m] = v.x; As[k+1][m] = v.y; As[k+2][m] = v.z; As[k+3][m] = v.w;
        }
        {
            int k = tx >> 4, n = (tx & 15) << 2;
            float4 v = *(const float4*)(Bp + (size_t)(k0 + k) * V_ + n);
            Bs[k][n+0] = v.x; Bs[k][n+1] = v.y; Bs[k][n+2] = v.z; Bs[k][n+3] = v.w;
        }
        __syncthreads();
        #pragma unroll
        for (int k = 0; k < 16; ++k) {
            float4 a = *(const float4*)&As[k][rr];
            float4 b = *(const float4*)&Bs[k][cc];
            acc[0][0] += a.x*b.x; acc[0][1] += a.x*b.y; acc[0][2] += a.x*b.z; acc[0][3] += a.x*b.w;
            acc[1][0] += a.y*b.x; acc[1][1] += a.y*b.y; acc[1][2] += a.y*b.z; acc[1][3] += a.y*b.w;
            acc[2][0] += a.z*b.x; acc[2][1] += a.z*b.y; acc[2][2] += a.z*b.z; acc[2][3] += a.z*b.w;
            acc[3][0] += a.w*b.x; acc[3][1] += a.w*b.y; acc[3][2] += a.w*b.z; acc[3][3] += a.w*b.w;
        }
        __syncthreads();
    }
    #pragma unroll
    for (int i = 0; i < 4; ++i)
        #pragma unroll
        for (int j = 0; j < 4; ++j)
            out[(size_t)(tt + rr + i) * V_ + vv + cc + j] = acc[i][j];
}

__global__ void k_embed_out(float* __restrict__ out) {
    int b = blockIdx.x, d = threadIdx.x;
    float s = 0.f;
    for (int t = 0; t < T_; ++t) s += g_x[((size_t)b * T_ + t) * D_ + d];
    out[(size_t)B_ * T_ * V_ + b * D_ + d] = s * (1.0f / T_);
}

__global__ void k_trace(float* __restrict__ out) {
    int idx = blockIdx.x * 256 + threadIdx.x;   // over B*NH*NN
    int bh = idx >> 12;
    int n  = idx & (NN - 1);
    const bf16* p = g_xypk + (size_t)bh * T_ * 8192 + ((size_t)(n >> 5) << 6) + (n & 31);
    float s = 0.f;
    for (int t = 0; t < T_; ++t) {
        const bf16* q = p + (size_t)t * 8192;
        s += __bfloat162float(q[0]) + __bfloat162float(q[32]);
    }
    out[(size_t)B_ * T_ * V_ + B_ * D_ + idx] = s * (1.0f / T_);
}

// ---------------- launch ----------------------------------------------------
extern "C" void kernel_launch(void* const* d_in, const int* in_sizes, int n_in,
                              void* d_out, int out_size) {
    (void)in_sizes; (void)n_in; (void)out_size;
    const int*   ids   = (const int*)d_in[0];
    const float* table = (const float*)d_in[1];
    const float* enc   = (const float*)d_in[2];
    const float* encv  = (const float*)d_in[3];
    const float* dec   = (const float*)d_in[4];
    const float* lmh   = (const float*)d_in[5];
    float* out = (float*)d_out;

    k_tables<<<(T_ * NH2) / 256, 256>>>();
    k_zero_spk<<<(int)((sizeof(bf16) * BH * T_ * 1024) / 16 / 256), 256>>>();
    k_tpack<<<dim3(NN/32, D_/32, NH), 256>>>(enc,  0);
    k_tpack<<<dim3(NN/32, D_/32, NH), 256>>>(encv, 1);
    k_tpack<<<dim3(D_/32, NN/32, NH), 256>>>(dec,  2);
    k_embed<<<B_ * T_, 256>>>(ids, table);
    k_tpack<<<dim3(D_/32, T_/32, B_), 256>>>(nullptr, 3);

    for (int l = 0; l < N_LAYER; ++l) {
        k_enc_tc  <<<dim3(NN/128, T_/128, BH), 256>>>(0);
        k_scores_tc<<<dim3(10, 4, BH), 256>>>();
        k_sreduce <<<dim3(16, 10, BH), 256>>>();
        k_ykv_tc  <<<dim3(D_/128, T_/128, BH), 256>>>();
        k_ln_ykv  <<<BH * T_, 256>>>();
        k_enc_tc  <<<dim3(NN/128, T_/128, BH), 256>>>(1);
        k_ymlp_tc <<<dim3(D_/128, T_/128, BH * 4), 256>>>();
        k_resid   <<<B_ * T_, 256>>>();
        k_tpack<<<dim3(D_/32, T_/32, B_), 256>>>(nullptr, 3);
    }
    k_logits<<<dim3(V_/64, (B_*T_)/64), 256>>>(lmh, out);
    k_embed_out<<<B_, 256>>>(out);
    k_trace<<<(B_ * NH * NN) / 256, 256>>>(out);
}